// round 12
// baseline (speedup 1.0000x reference)
#include <cuda_runtime.h>
#include <cuda_bf16.h>
#include <math.h>
#include <stdint.h>

#define NN 50000
#define NE 200000

// ---------------- scratch (device globals; no allocation) ----------------
__device__ float g_node_h[(size_t)NN * 128];
__device__ float g_agg[(size_t)NN * 128];     // per-layer gather output (write-only)
__device__ float g_agg_e[(size_t)NN * 128];   // layer-invariant: sum of edge_h into dst
__device__ float g_ef_sum[(size_t)NN * 64];   // sum of raw edge features into dst
__device__ float g_indeg[NN];
__device__ float g_a[NN];                     // node_h . w0
__device__ float g_b[NN];                     // node_h . w1
__device__ float g_edot[NE];                  // edge_h . w2 (layer-invariant)
__device__ float g_ve[64];                    // W_edge @ w2
__device__ float g_vc;                        // b_edge . w2
// CSR-by-dst (built per launch; edge_indices is a constant input)
__device__ int g_deg[NN];
__device__ int g_row_ptr[NN + 1];
__device__ int g_cursor[NN];
__device__ int g_perm_src[NE];
__device__ int g_perm_eid[NE];
// pre-split bf16 weight planes, [n][k] layout (B operand, col-major)
__device__ __nv_bfloat16 g_wth_node[128 * 128], g_wtl_node[128 * 128];
__device__ __nv_bfloat16 g_wth_edge[128 * 64],  g_wtl_edge[128 * 64];
__device__ __nv_bfloat16 g_wth_gnn[3 * 128 * 256], g_wtl_gnn[3 * 128 * 256];

__device__ __forceinline__ void split_store(float x, __nv_bfloat16* ph, __nv_bfloat16* pl) {
    __nv_bfloat16 h = __float2bfloat16(x);
    *ph = h;
    *pl = __float2bfloat16(x - __bfloat162float(h));
}

// ---------------- fused prologue: zeros + transposes + ve ----------------
// flat index space:
//  [0, 800000)            zero g_ef_sum (float4; NN*64/4 = 800000)
//  [800000, 850000)       zero g_deg (int)
//  [850000, 900000)       zero g_cursor (int)
//  [900000, 916384)       transpose+split W_node (16384)
//  [916384, 924576)       transpose+split W_edge (8192)
//  [924576, 1022880)      transpose+split W_gnn (98304)
//  [1022880, 1022944)     ve (64)
#define PREP_TOTAL 1022944
__global__ void prep_kernel(const float* __restrict__ W_node,
                            const float* __restrict__ W_edge,
                            const float* __restrict__ W_gnn,
                            const float* __restrict__ b_edge,
                            const float* __restrict__ W_top)
{
    int i = blockIdx.x * blockDim.x + threadIdx.x;
    if (i < 800000) {
        reinterpret_cast<float4*>(g_ef_sum)[i] = make_float4(0.f, 0.f, 0.f, 0.f);
    } else if (i < 850000) {
        g_deg[i - 800000] = 0;
    } else if (i < 900000) {
        g_cursor[i - 850000] = 0;
    } else if (i < 916384) {
        int j = i - 900000;
        int k = j >> 7, n = j & 127;
        split_store(W_node[j], &g_wth_node[n * 128 + k], &g_wtl_node[n * 128 + k]);
    } else if (i < 924576) {
        int j = i - 916384;
        int k = j >> 7, n = j & 127;
        split_store(W_edge[j], &g_wth_edge[n * 64 + k], &g_wtl_edge[n * 64 + k]);
    } else if (i < 1022880) {
        int j = i - 924576;
        int l = j / 32768, r = j % 32768;
        int k = r >> 7, n = r & 127;
        split_store(W_gnn[j], &g_wth_gnn[l * 32768 + n * 256 + k],
                              &g_wtl_gnn[l * 32768 + n * 256 + k]);
    } else if (i < 1022944) {
        int k = i - 1022880;
        float s = 0.f;
        for (int n = 0; n < 128; n++) s += W_edge[k * 128 + n] * W_top[256 + n];
        g_ve[k] = s;
        if (k == 0) {
            float c = 0.f;
            for (int n = 0; n < 128; n++) c += b_edge[n] * W_top[256 + n];
            g_vc = c;
        }
    }
}

// ---------------- edge feature sum + edot + degree (16 lanes per edge) ----------------
__global__ void __launch_bounds__(256)
edge_sum_kernel(const float* __restrict__ ef, const int* __restrict__ dst_idx)
{
    int t = blockIdx.x * blockDim.x + threadIdx.x;
    int e = t >> 4;
    int l = t & 15;
    if (e >= NE) return;

    float4 v  = *reinterpret_cast<const float4*>(ef + (size_t)e * 64 + l * 4);
    float4 ve = *reinterpret_cast<const float4*>(g_ve + l * 4);
    float p = v.x * ve.x + v.y * ve.y + v.z * ve.z + v.w * ve.w;
#pragma unroll
    for (int o = 1; o < 16; o <<= 1) p += __shfl_xor_sync(0xffffffffu, p, o);

    int d = dst_idx[e];
    if (l == 0) {
        g_edot[e] = p + g_vc;
        atomicAdd(&g_deg[d], 1);
    }
    atomicAdd(reinterpret_cast<float4*>(g_ef_sum + (size_t)d * 64 + l * 4), v);
}

// ---------------- exclusive scan of degrees -> row_ptr (single block) ----------------
__global__ void __launch_bounds__(1024)
scan_kernel()
{
    __shared__ int warp_sums[32];
    __shared__ int s_running;
    const int t = threadIdx.x, lane = t & 31, w = t >> 5;
    if (t == 0) s_running = 0;
    __syncthreads();

    for (int base = 0; base < NN; base += 1024) {
        int idx = base + t;
        int v = (idx < NN) ? g_deg[idx] : 0;
        int sc = v;
#pragma unroll
        for (int o = 1; o < 32; o <<= 1) {
            int x = __shfl_up_sync(0xffffffffu, sc, o);
            if (lane >= o) sc += x;
        }
        if (lane == 31) warp_sums[w] = sc;
        __syncthreads();
        if (w == 0) {
            int ws = warp_sums[lane];
#pragma unroll
            for (int o = 1; o < 32; o <<= 1) {
                int x = __shfl_up_sync(0xffffffffu, ws, o);
                if (lane >= o) ws += x;
            }
            warp_sums[lane] = ws;
        }
        __syncthreads();
        int warp_off = (w > 0) ? warp_sums[w - 1] : 0;
        int excl = s_running + warp_off + sc - v;
        if (idx < NN) {
            g_row_ptr[idx] = excl;
            g_indeg[idx] = (float)v;
        }
        __syncthreads();
        if (t == 0) s_running += warp_sums[31];
        __syncthreads();
    }
    if (t == 0) g_row_ptr[NN] = s_running;
}

// ---------------- scatter edges into CSR order ----------------
__global__ void __launch_bounds__(256)
perm_kernel(const int* __restrict__ src_idx, const int* __restrict__ dst_idx)
{
    int e = blockIdx.x * blockDim.x + threadIdx.x;
    if (e >= NE) return;
    int d = dst_idx[e];
    int pos = g_row_ptr[d] + atomicAdd(&g_cursor[d], 1);
    g_perm_src[pos] = src_idx[e];
    g_perm_eid[pos] = e;
}

// ---------------- per-layer gather: agg[n] = sum over incoming edges ----------------
__global__ void __launch_bounds__(256)
gather_kernel(const float* __restrict__ b_top, float* __restrict__ w_out)
{
    int n = (blockIdx.x * blockDim.x + threadIdx.x) >> 5;
    int lane = threadIdx.x & 31;
    if (n >= NN) return;

    int beg = g_row_ptr[n];
    int end = g_row_ptr[n + 1];
    float bt = g_b[n] + b_top[0];

    float4 acc = make_float4(0.f, 0.f, 0.f, 0.f);
    for (int j = beg; j < end; j++) {
        int s   = g_perm_src[j];
        int eid = g_perm_eid[j];
        float gte = g_a[s] + bt + g_edot[eid];
        float wgt = 1.f / (1.f + __expf(-gte));
        float4 sv = *reinterpret_cast<const float4*>(g_node_h + (size_t)s * 128 + lane * 4);
        acc.x += wgt * sv.x; acc.y += wgt * sv.y;
        acc.z += wgt * sv.z; acc.w += wgt * sv.w;
        if (w_out != nullptr && lane == 0) w_out[eid] = wgt;
    }
    *reinterpret_cast<float4*>(g_agg + (size_t)n * 128 + lane * 4) = acc;
}

// ---------------- mma / ldmatrix / cp.async / bf16 helpers ----------------
#define MMA_BF16(d, a0, a1, a2, a3, b0, b1)                                    \
    asm volatile(                                                              \
        "mma.sync.aligned.m16n8k16.row.col.f32.bf16.bf16.f32 "                 \
        "{%0,%1,%2,%3}, {%4,%5,%6,%7}, {%8,%9}, {%0,%1,%2,%3};"                \
        : "+f"((d)[0]), "+f"((d)[1]), "+f"((d)[2]), "+f"((d)[3])               \
        : "r"(a0), "r"(a1), "r"(a2), "r"(a3), "r"(b0), "r"(b1))

#define LDSM_X4(R, addr)                                                       \
    asm volatile("ldmatrix.sync.aligned.m8n8.x4.shared.b16 {%0,%1,%2,%3}, [%4];" \
        : "=r"((R)[0]), "=r"((R)[1]), "=r"((R)[2]), "=r"((R)[3]) : "r"(addr))

#define ST_V2(addr, x, y)                                                      \
    asm volatile("st.shared.v2.u32 [%0], {%1,%2};" :: "r"(addr), "r"(x), "r"(y))

#define CP_ASYNC16(saddr, gptr) \
    asm volatile("cp.async.cg.shared.global [%0], [%1], 16;" :: "r"(saddr), "l"(gptr))
#define CP_COMMIT() asm volatile("cp.async.commit_group;")
#define CP_WAIT0()  asm volatile("cp.async.wait_group 0;")

__device__ __forceinline__ uint32_t bf16x2_split(float2 f, float2& rem) {
    uint32_t h;
    asm("cvt.rn.bf16x2.f32 %0, %1, %2;" : "=r"(h) : "f"(f.y), "f"(f.x));
    float hx = __uint_as_float(h << 16);
    float hy = __uint_as_float(h & 0xFFFF0000u);
    rem.x = f.x - hx;
    rem.y = f.y - hy;
    return h;
}
__device__ __forceinline__ uint32_t bf16x2_pack(float2 f) {
    uint32_t h;
    asm("cvt.rn.bf16x2.f32 %0, %1, %2;" : "=r"(h) : "f"(f.y), "f"(f.x));
    return h;
}

// =====================================================================
// Fused bf16x2-split GEMM.
// MODE 0 (node embed):  write g_node_h; a = y.w0, b = y.w1
// MODE 2 (update):      A = [node_h | g_agg + g_agg_e]; x = node_h + (acc+bias);
//                       LayerNorm+ReLU -> dest; opt a,b dots
// MODE 3 (agg_e):       A = ef_sum [NN,64]; out = acc + indeg[r]*bias -> dest
// =====================================================================
template <int KTOT, int MODE>
__global__ void __launch_bounds__(256, 2)
mma_gemm_kernel(const float* __restrict__ A,
                const __nv_bfloat16* __restrict__ WTH,
                const __nv_bfloat16* __restrict__ WTL,
                const float* __restrict__ bias,
                int M,
                const float* __restrict__ aux,    // MODE0/2: W_top; MODE3: indeg
                const float* __restrict__ lns,
                const float* __restrict__ lnb,
                float* __restrict__ dest,
                int doab)
{
    extern __shared__ float smem[];
    constexpr int NCH = KTOT / 32;
    constexpr int PITCH = 80;
    constexpr int PLANE = 128 * PITCH;
    constexpr int OFF_AH = 0, OFF_AL = PLANE, OFF_BH = 2 * PLANE, OFF_BL = 3 * PLANE;
    constexpr int BUF = 4 * PLANE;

    const int tid   = threadIdx.x;
    const int wid   = tid >> 5;
    const int lane  = tid & 31;
    const int warpM = wid >> 1;
    const int warpN = wid & 1;
    const int lq    = lane >> 2;
    const int lr    = lane & 3;
    const int row0  = blockIdx.x * 128;

    const uint32_t sbase = (uint32_t)__cvta_generic_to_shared(smem);

    float acc[2][8][4];
#pragma unroll
    for (int i = 0; i < 2; i++)
#pragma unroll
        for (int j = 0; j < 8; j++)
#pragma unroll
            for (int q = 0; q < 4; q++) acc[i][j][q] = 0.f;

    float4 va[4];
    auto loadA = [&](int kc) {
#pragma unroll
        for (int l = 0; l < 4; l++) {
            int idx = tid + l * 256;
            int r = idx >> 3;
            int kq = (idx & 7) * 4;
            int grow = row0 + r;
            if (grow >= M) grow = M - 1;
            if (MODE == 2) {
                if (kc < 4) {
                    va[l] = *reinterpret_cast<const float4*>(
                        g_node_h + (size_t)grow * 128 + kc * 32 + kq);
                } else {
                    float4 x = *reinterpret_cast<const float4*>(
                        g_agg + (size_t)grow * 128 + (kc - 4) * 32 + kq);
                    float4 y = *reinterpret_cast<const float4*>(
                        g_agg_e + (size_t)grow * 128 + (kc - 4) * 32 + kq);
                    va[l] = make_float4(x.x + y.x, x.y + y.y, x.z + y.z, x.w + y.w);
                }
            } else {
                va[l] = *reinterpret_cast<const float4*>(
                    A + (size_t)grow * KTOT + kc * 32 + kq);
            }
        }
    };
    auto storeA = [&](int buf) {
        const uint32_t bufo = sbase + buf * BUF;
#pragma unroll
        for (int l = 0; l < 4; l++) {
            int idx = tid + l * 256;
            int r = idx >> 3;
            int kq = (idx & 7) * 4;
            uint32_t off = (uint32_t)(r * PITCH + kq * 2);
            float2 rm0, rm1;
            uint32_t h0 = bf16x2_split(make_float2(va[l].x, va[l].y), rm0);
            uint32_t h1 = bf16x2_split(make_float2(va[l].z, va[l].w), rm1);
            ST_V2(bufo + OFF_AH + off, h0, h1);
            ST_V2(bufo + OFF_AL + off, bf16x2_pack(rm0), bf16x2_pack(rm1));
        }
    };
    auto fillB = [&](int kc, int buf) {
        const uint32_t bufo = sbase + buf * BUF;
#pragma unroll
        for (int l = 0; l < 2; l++) {
            int gr = tid + l * 256;
            int row = gr >> 2;
            int seg = gr & 3;
            uint32_t soff = (uint32_t)(row * PITCH + seg * 16);
            const __nv_bfloat16* sh = WTH + (size_t)row * KTOT + kc * 32 + seg * 8;
            const __nv_bfloat16* sl = WTL + (size_t)row * KTOT + kc * 32 + seg * 8;
            CP_ASYNC16(bufo + OFF_BH + soff, sh);
            CP_ASYNC16(bufo + OFF_BL + soff, sl);
        }
        CP_COMMIT();
    };

    loadA(0);
    fillB(0, 0);
    storeA(0);
    CP_WAIT0();
    __syncthreads();

    const int g   = lane & 15;
    const int hh  = lane >> 4;
    const int q8  = lane & 7;
    const int seg = (lane >> 3) & 3;

    for (int kc = 0; kc < NCH; kc++) {
        const int cur = kc & 1;
        if (kc + 1 < NCH) {
            loadA(kc + 1);
            fillB(kc + 1, cur ^ 1);
        }

        const uint32_t bufo = sbase + cur * BUF;
#pragma unroll
        for (int ks = 0; ks < 2; ks++) {
            uint32_t ah[2][4], al[2][4];
#pragma unroll
            for (int tm = 0; tm < 2; tm++) {
                uint32_t ra = bufo + OFF_AH
                    + (uint32_t)((warpM * 32 + tm * 16 + g) * PITCH + ks * 32 + hh * 16);
                LDSM_X4(ah[tm], ra);
                LDSM_X4(al[tm], ra + (OFF_AL - OFF_AH));
            }
#pragma unroll
            for (int p = 0; p < 4; p++) {
                int n = warpN * 64 + (2 * p + (seg >> 1)) * 8 + q8;
                uint32_t rb = bufo + OFF_BH
                    + (uint32_t)(n * PITCH + ks * 32 + (seg & 1) * 16);
                uint32_t bh[4], bl[4];
                LDSM_X4(bh, rb);
                LDSM_X4(bl, rb + (OFF_BL - OFF_BH));
                MMA_BF16(acc[0][2 * p],     ah[0][0], ah[0][1], ah[0][2], ah[0][3], bh[0], bh[1]);
                MMA_BF16(acc[1][2 * p],     ah[1][0], ah[1][1], ah[1][2], ah[1][3], bh[0], bh[1]);
                MMA_BF16(acc[0][2 * p + 1], ah[0][0], ah[0][1], ah[0][2], ah[0][3], bh[2], bh[3]);
                MMA_BF16(acc[1][2 * p + 1], ah[1][0], ah[1][1], ah[1][2], ah[1][3], bh[2], bh[3]);
                MMA_BF16(acc[0][2 * p],     al[0][0], al[0][1], al[0][2], al[0][3], bh[0], bh[1]);
                MMA_BF16(acc[1][2 * p],     al[1][0], al[1][1], al[1][2], al[1][3], bh[0], bh[1]);
                MMA_BF16(acc[0][2 * p + 1], al[0][0], al[0][1], al[0][2], al[0][3], bh[2], bh[3]);
                MMA_BF16(acc[1][2 * p + 1], al[1][0], al[1][1], al[1][2], al[1][3], bh[2], bh[3]);
                MMA_BF16(acc[0][2 * p],     ah[0][0], ah[0][1], ah[0][2], ah[0][3], bl[0], bl[1]);
                MMA_BF16(acc[1][2 * p],     ah[1][0], ah[1][1], ah[1][2], ah[1][3], bl[0], bl[1]);
                MMA_BF16(acc[0][2 * p + 1], ah[0][0], ah[0][1], ah[0][2], ah[0][3], bl[2], bl[3]);
                MMA_BF16(acc[1][2 * p + 1], ah[1][0], ah[1][1], ah[1][2], ah[1][3], bl[2], bl[3]);
            }
        }
        if (kc + 1 < NCH) storeA(cur ^ 1);
        CP_WAIT0();
        __syncthreads();
    }

    // ---------------- epilogue ----------------
    if (MODE != 3) {
#pragma unroll
        for (int tn = 0; tn < 8; tn++) {
            int col = warpN * 64 + tn * 8 + lr * 2;
            float bx = bias[col], by = bias[col + 1];
#pragma unroll
            for (int tm = 0; tm < 2; tm++) {
                acc[tm][tn][0] += bx; acc[tm][tn][1] += by;
                acc[tm][tn][2] += bx; acc[tm][tn][3] += by;
            }
        }
    }
    int rl[2][2], rg[2][2];
#pragma unroll
    for (int tm = 0; tm < 2; tm++) {
        rl[tm][0] = warpM * 32 + tm * 16 + lq;
        rl[tm][1] = rl[tm][0] + 8;
        rg[tm][0] = row0 + rl[tm][0];
        rg[tm][1] = row0 + rl[tm][1];
    }

    float* red0 = smem;
    float* red1 = smem + 128;

    if (MODE == 0) {
        float pa[2][2] = {{0,0},{0,0}}, pb[2][2] = {{0,0},{0,0}};
#pragma unroll
        for (int tn = 0; tn < 8; tn++) {
            int col = warpN * 64 + tn * 8 + lr * 2;
            float w0x = aux[col], w0y = aux[col + 1];
            float w1x = aux[128 + col], w1y = aux[128 + col + 1];
#pragma unroll
            for (int tm = 0; tm < 2; tm++) {
#pragma unroll
                for (int h = 0; h < 2; h++) {
                    float vx = acc[tm][tn][h * 2], vy = acc[tm][tn][h * 2 + 1];
                    if (rg[tm][h] < M)
                        *reinterpret_cast<float2*>(g_node_h + (size_t)rg[tm][h] * 128 + col)
                            = make_float2(vx, vy);
                    pa[tm][h] += vx * w0x + vy * w0y;
                    pb[tm][h] += vx * w1x + vy * w1y;
                }
            }
        }
        if (tid < 128) { red0[tid] = 0.f; red1[tid] = 0.f; }
        __syncthreads();
#pragma unroll
        for (int tm = 0; tm < 2; tm++)
#pragma unroll
            for (int h = 0; h < 2; h++) {
#pragma unroll
                for (int o = 1; o <= 2; o <<= 1) {
                    pa[tm][h] += __shfl_xor_sync(0xffffffffu, pa[tm][h], o);
                    pb[tm][h] += __shfl_xor_sync(0xffffffffu, pb[tm][h], o);
                }
                if (lr == 0) {
                    atomicAdd(&red0[rl[tm][h]], pa[tm][h]);
                    atomicAdd(&red1[rl[tm][h]], pb[tm][h]);
                }
            }
        __syncthreads();
        if (tid < 128 && row0 + tid < M) {
            g_a[row0 + tid] = red0[tid];
            g_b[row0 + tid] = red1[tid];
        }
    }
    else if (MODE == 3) {
        float ind[2][2];
#pragma unroll
        for (int tm = 0; tm < 2; tm++)
#pragma unroll
            for (int h = 0; h < 2; h++)
                ind[tm][h] = (rg[tm][h] < M) ? aux[rg[tm][h]] : 0.f;
#pragma unroll
        for (int tn = 0; tn < 8; tn++) {
            int col = warpN * 64 + tn * 8 + lr * 2;
            float bx = bias[col], by = bias[col + 1];
#pragma unroll
            for (int tm = 0; tm < 2; tm++) {
#pragma unroll
                for (int h = 0; h < 2; h++) {
                    if (rg[tm][h] < M) {
                        float2 v = make_float2(acc[tm][tn][h * 2] + ind[tm][h] * bx,
                                               acc[tm][tn][h * 2 + 1] + ind[tm][h] * by);
                        *reinterpret_cast<float2*>(dest + (size_t)rg[tm][h] * 128 + col) = v;
                    }
                }
            }
        }
    }
    else {
        float ps[2][2] = {{0,0},{0,0}}, pq[2][2] = {{0,0},{0,0}};
#pragma unroll
        for (int tn = 0; tn < 8; tn++) {
            int col = warpN * 64 + tn * 8 + lr * 2;
#pragma unroll
            for (int tm = 0; tm < 2; tm++) {
#pragma unroll
                for (int h = 0; h < 2; h++) {
                    float2 res = (rg[tm][h] < M)
                        ? *reinterpret_cast<const float2*>(g_node_h + (size_t)rg[tm][h] * 128 + col)
                        : make_float2(0.f, 0.f);
                    float x0 = acc[tm][tn][h * 2] + res.x;
                    float x1 = acc[tm][tn][h * 2 + 1] + res.y;
                    acc[tm][tn][h * 2] = x0;
                    acc[tm][tn][h * 2 + 1] = x1;
                    ps[tm][h] += x0 + x1;
                    pq[tm][h] += x0 * x0 + x1 * x1;
                }
            }
        }
        if (tid < 128) { red0[tid] = 0.f; red1[tid] = 0.f; }
        __syncthreads();
#pragma unroll
        for (int tm = 0; tm < 2; tm++)
#pragma unroll
            for (int h = 0; h < 2; h++) {
#pragma unroll
                for (int o = 1; o <= 2; o <<= 1) {
                    ps[tm][h] += __shfl_xor_sync(0xffffffffu, ps[tm][h], o);
                    pq[tm][h] += __shfl_xor_sync(0xffffffffu, pq[tm][h], o);
                }
                if (lr == 0) {
                    atomicAdd(&red0[rl[tm][h]], ps[tm][h]);
                    atomicAdd(&red1[rl[tm][h]], pq[tm][h]);
                }
            }
        __syncthreads();
        float mean_[2][2], inv_[2][2];
#pragma unroll
        for (int tm = 0; tm < 2; tm++)
#pragma unroll
            for (int h = 0; h < 2; h++) {
                float m = red0[rl[tm][h]] * (1.f / 128.f);
                float var = red1[rl[tm][h]] * (1.f / 128.f) - m * m;
                mean_[tm][h] = m;
                inv_[tm][h] = rsqrtf(fmaxf(var, 0.f) + 1e-6f);
            }
        float pa[2][2] = {{0,0},{0,0}}, pb[2][2] = {{0,0},{0,0}};
#pragma unroll
        for (int tn = 0; tn < 8; tn++) {
            int col = warpN * 64 + tn * 8 + lr * 2;
            float scx = lns[col], scy = lns[col + 1];
            float bix = lnb[col], biy = lnb[col + 1];
            float w0x = aux[col], w0y = aux[col + 1];
            float w1x = aux[128 + col], w1y = aux[128 + col + 1];
#pragma unroll
            for (int tm = 0; tm < 2; tm++) {
#pragma unroll
                for (int h = 0; h < 2; h++) {
                    float y0 = fmaxf(0.f, (acc[tm][tn][h * 2] - mean_[tm][h]) * inv_[tm][h] * scx + bix);
                    float y1 = fmaxf(0.f, (acc[tm][tn][h * 2 + 1] - mean_[tm][h]) * inv_[tm][h] * scy + biy);
                    if (rg[tm][h] < M)
                        *reinterpret_cast<float2*>(dest + (size_t)rg[tm][h] * 128 + col)
                            = make_float2(y0, y1);
                    pa[tm][h] += y0 * w0x + y1 * w0y;
                    pb[tm][h] += y0 * w1x + y1 * w1y;
                }
            }
        }
        if (doab) {
            __syncthreads();
            if (tid < 128) { red0[tid] = 0.f; red1[tid] = 0.f; }
            __syncthreads();
#pragma unroll
            for (int tm = 0; tm < 2; tm++)
#pragma unroll
                for (int h = 0; h < 2; h++) {
#pragma unroll
                    for (int o = 1; o <= 2; o <<= 1) {
                        pa[tm][h] += __shfl_xor_sync(0xffffffffu, pa[tm][h], o);
                        pb[tm][h] += __shfl_xor_sync(0xffffffffu, pb[tm][h], o);
                    }
                    if (lr == 0) {
                        atomicAdd(&red0[rl[tm][h]], pa[tm][h]);
                        atomicAdd(&red1[rl[tm][h]], pb[tm][h]);
                    }
                }
            __syncthreads();
            if (tid < 128 && row0 + tid < M) {
                g_a[row0 + tid] = red0[tid];
                g_b[row0 + tid] = red1[tid];
            }
        }
    }
}

// ---------------- launch ----------------
extern "C" void kernel_launch(void* const* d_in, const int* in_sizes, int n_in,
                              void* d_out, int out_size)
{
    const float* nf     = (const float*)d_in[0];
    const float* ef     = (const float*)d_in[1];
    const int*   ei     = (const int*)  d_in[2];
    const float* W_node = (const float*)d_in[3];
    const float* b_node = (const float*)d_in[4];
    const float* W_edge = (const float*)d_in[5];
    const float* b_edge = (const float*)d_in[6];
    const float* W_gnn  = (const float*)d_in[7];
    const float* b_gnn  = (const float*)d_in[8];
    const float* W_top  = (const float*)d_in[9];
    const float* b_top  = (const float*)d_in[10];
    const float* ln_s   = (const float*)d_in[11];
    const float* ln_b   = (const float*)d_in[12];

    float* out       = (float*)d_out;
    float* out_nodes = out;
    float* out_w     = out + (size_t)NN * 128;

    const int* src = ei;
    const int* dst = ei + NE;

    const int SMEM_SZ = 2 * 4 * 128 * 80;   // 81920 B
    cudaFuncSetAttribute(mma_gemm_kernel<128, 0>, cudaFuncAttributeMaxDynamicSharedMemorySize, SMEM_SZ);
    cudaFuncSetAttribute(mma_gemm_kernel<64, 3>,  cudaFuncAttributeMaxDynamicSharedMemorySize, SMEM_SZ);
    cudaFuncSetAttribute(mma_gemm_kernel<256, 2>, cudaFuncAttributeMaxDynamicSharedMemorySize, SMEM_SZ);

    __nv_bfloat16 *wthn = nullptr, *wtln = nullptr, *wthe = nullptr, *wtle = nullptr;
    __nv_bfloat16 *wthg = nullptr, *wtlg = nullptr;
    cudaGetSymbolAddress((void**)&wthn, g_wth_node);
    cudaGetSymbolAddress((void**)&wtln, g_wtl_node);
    cudaGetSymbolAddress((void**)&wthe, g_wth_edge);
    cudaGetSymbolAddress((void**)&wtle, g_wtl_edge);
    cudaGetSymbolAddress((void**)&wthg, g_wth_gnn);
    cudaGetSymbolAddress((void**)&wtlg, g_wtl_gnn);
    float* nodeh = nullptr; float* aggep = nullptr;
    float* efsum = nullptr; float* indeg = nullptr;
    cudaGetSymbolAddress((void**)&nodeh, g_node_h);
    cudaGetSymbolAddress((void**)&aggep, g_agg_e);
    cudaGetSymbolAddress((void**)&efsum, g_ef_sum);
    cudaGetSymbolAddress((void**)&indeg, g_indeg);

    // fused prologue (zeros + transposes + ve)
    prep_kernel<<<(PREP_TOTAL + 255) / 256, 256>>>(W_node, W_edge, W_gnn, b_edge, W_top);

    // edge feature sum + edot + degrees
    edge_sum_kernel<<<(NE * 16 + 255) / 256, 256>>>(ef, dst);

    // CSR build: scan degrees -> row_ptr; scatter edges
    scan_kernel<<<1, 1024>>>();
    perm_kernel<<<(NE + 255) / 256, 256>>>(src, dst);

    // node embed (+ a,b dots)
    mma_gemm_kernel<128, 0><<<(NN + 127) / 128, 256, SMEM_SZ>>>(
        nf, wthn, wtln, b_node, NN, W_top, nullptr, nullptr, nullptr, 0);
    // agg_e = ef_sum @ W_edge + indeg * b_edge  (tiny GEMM)
    mma_gemm_kernel<64, 3><<<(NN + 127) / 128, 256, SMEM_SZ>>>(
        efsum, wthe, wtle, b_edge, NN, indeg, nullptr, nullptr, aggep, 0);

    for (int i = 0; i < 3; i++) {
        gather_kernel<<<(NN * 32 + 255) / 256, 256>>>(
            b_top, (i == 2) ? out_w : nullptr);
        mma_gemm_kernel<256, 2><<<(NN + 127) / 128, 256, SMEM_SZ>>>(
            nullptr, wthg + (size_t)i * 128 * 256, wtlg + (size_t)i * 128 * 256,
            b_gnn + i * 128, NN,
            W_top, ln_s + i * 128, ln_b + i * 128,
            (i == 2) ? out_nodes : nodeh, (i < 2) ? 1 : 0);
    }
}

// round 13
// speedup vs baseline: 1.0426x; 1.0426x over previous
#include <cuda_runtime.h>
#include <cuda_bf16.h>
#include <math.h>
#include <stdint.h>

#define NN 50000
#define NE 200000

// ---------------- scratch (device globals; no allocation) ----------------
__device__ float g_node_h[(size_t)NN * 128];
__device__ float g_agg[(size_t)NN * 128];     // per-layer scatter target (zeroed)
__device__ float g_agg_e[(size_t)NN * 128];   // layer-invariant: sum of edge_h into dst
__device__ float g_ef_sum[(size_t)NN * 64];   // sum of raw edge features into dst
__device__ float g_indeg[NN];
__device__ float g_a[NN];                     // node_h . w0
__device__ float g_b[NN];                     // node_h . w1
__device__ float g_edot[NE];                  // edge_h . w2 (layer-invariant)
__device__ float g_ve[64];                    // W_edge @ w2
__device__ float g_vc;                        // b_edge . w2
// pre-split bf16 weight planes, [n][k] layout (B operand, col-major)
__device__ __nv_bfloat16 g_wth_node[128 * 128], g_wtl_node[128 * 128];
__device__ __nv_bfloat16 g_wth_edge[128 * 64],  g_wtl_edge[128 * 64];
__device__ __nv_bfloat16 g_wth_gnn[3 * 128 * 256], g_wtl_gnn[3 * 128 * 256];

__device__ __forceinline__ void split_store(float x, __nv_bfloat16* ph, __nv_bfloat16* pl) {
    __nv_bfloat16 h = __float2bfloat16(x);
    *ph = h;
    *pl = __float2bfloat16(x - __bfloat162float(h));
}

// ---------------- fused prologue: zeros + transposes + ve ----------------
// flat index space (g_ef_sum = NN*64 floats = 800000 float4):
//  [0, 800000)          zero g_ef_sum (float4)
//  [800000, 812500)     zero g_indeg (float4)
//  [812500, 828884)     transpose+split W_node (16384)
//  [828884, 837076)     transpose+split W_edge (8192)
//  [837076, 935380)     transpose+split W_gnn (98304)
//  [935380, 935444)     ve (64)
#define PREP_TOTAL 935444
__global__ void prep_kernel(const float* __restrict__ W_node,
                            const float* __restrict__ W_edge,
                            const float* __restrict__ W_gnn,
                            const float* __restrict__ b_edge,
                            const float* __restrict__ W_top)
{
    int i = blockIdx.x * blockDim.x + threadIdx.x;
    if (i < 800000) {
        reinterpret_cast<float4*>(g_ef_sum)[i] = make_float4(0.f, 0.f, 0.f, 0.f);
    } else if (i < 812500) {
        reinterpret_cast<float4*>(g_indeg)[i - 800000] = make_float4(0.f, 0.f, 0.f, 0.f);
    } else if (i < 828884) {
        int j = i - 812500;
        int k = j >> 7, n = j & 127;
        split_store(W_node[j], &g_wth_node[n * 128 + k], &g_wtl_node[n * 128 + k]);
    } else if (i < 837076) {
        int j = i - 828884;
        int k = j >> 7, n = j & 127;
        split_store(W_edge[j], &g_wth_edge[n * 64 + k], &g_wtl_edge[n * 64 + k]);
    } else if (i < 935380) {
        int j = i - 837076;
        int l = j / 32768, r = j % 32768;
        int k = r >> 7, n = r & 127;
        split_store(W_gnn[j], &g_wth_gnn[l * 32768 + n * 256 + k],
                              &g_wtl_gnn[l * 32768 + n * 256 + k]);
    } else if (i < 935444) {
        int k = i - 935380;
        float s = 0.f;
        for (int n = 0; n < 128; n++) s += W_edge[k * 128 + n] * W_top[256 + n];
        g_ve[k] = s;
        if (k == 0) {
            float c = 0.f;
            for (int n = 0; n < 128; n++) c += b_edge[n] * W_top[256 + n];
            g_vc = c;
        }
    }
}

// ---------------- edge feature sum + edot (16 lanes per edge) ----------------
__global__ void __launch_bounds__(256)
edge_sum_kernel(const float* __restrict__ ef, const int* __restrict__ dst_idx)
{
    int t = blockIdx.x * blockDim.x + threadIdx.x;
    int e = t >> 4;
    int l = t & 15;
    if (e >= NE) return;

    float4 v  = *reinterpret_cast<const float4*>(ef + (size_t)e * 64 + l * 4);
    float4 ve = *reinterpret_cast<const float4*>(g_ve + l * 4);
    float p = v.x * ve.x + v.y * ve.y + v.z * ve.z + v.w * ve.w;
#pragma unroll
    for (int o = 1; o < 16; o <<= 1) p += __shfl_xor_sync(0xffffffffu, p, o);

    int d = dst_idx[e];
    if (l == 0) {
        g_edot[e] = p + g_vc;
        atomicAdd(&g_indeg[d], 1.f);
    }
    atomicAdd(reinterpret_cast<float4*>(g_ef_sum + (size_t)d * 64 + l * 4), v);
}

// ---------------- zero helper ----------------
__global__ void zero_buf_kernel(float* __restrict__ p, int n4)
{
    float4 z = make_float4(0.f, 0.f, 0.f, 0.f);
    for (int i = blockIdx.x * blockDim.x + threadIdx.x; i < n4; i += gridDim.x * blockDim.x)
        reinterpret_cast<float4*>(p)[i] = z;
}

// ---------------- mma / ldmatrix / cp.async / bf16 helpers ----------------
#define MMA_BF16(d, a0, a1, a2, a3, b0, b1)                                    \
    asm volatile(                                                              \
        "mma.sync.aligned.m16n8k16.row.col.f32.bf16.bf16.f32 "                 \
        "{%0,%1,%2,%3}, {%4,%5,%6,%7}, {%8,%9}, {%0,%1,%2,%3};"                \
        : "+f"((d)[0]), "+f"((d)[1]), "+f"((d)[2]), "+f"((d)[3])               \
        : "r"(a0), "r"(a1), "r"(a2), "r"(a3), "r"(b0), "r"(b1))

#define LDSM_X4(R, addr)                                                       \
    asm volatile("ldmatrix.sync.aligned.m8n8.x4.shared.b16 {%0,%1,%2,%3}, [%4];" \
        : "=r"((R)[0]), "=r"((R)[1]), "=r"((R)[2]), "=r"((R)[3]) : "r"(addr))

#define ST_V2(addr, x, y)                                                      \
    asm volatile("st.shared.v2.u32 [%0], {%1,%2};" :: "r"(addr), "r"(x), "r"(y))

#define CP_ASYNC16(saddr, gptr) \
    asm volatile("cp.async.cg.shared.global [%0], [%1], 16;" :: "r"(saddr), "l"(gptr))
#define CP_COMMIT() asm volatile("cp.async.commit_group;")
#define CP_WAIT0()  asm volatile("cp.async.wait_group 0;")

__device__ __forceinline__ uint32_t bf16x2_split(float2 f, float2& rem) {
    uint32_t h;
    asm("cvt.rn.bf16x2.f32 %0, %1, %2;" : "=r"(h) : "f"(f.y), "f"(f.x));
    float hx = __uint_as_float(h << 16);
    float hy = __uint_as_float(h & 0xFFFF0000u);
    rem.x = f.x - hx;
    rem.y = f.y - hy;
    return h;
}
__device__ __forceinline__ uint32_t bf16x2_pack(float2 f) {
    uint32_t h;
    asm("cvt.rn.bf16x2.f32 %0, %1, %2;" : "=r"(h) : "f"(f.y), "f"(f.x));
    return h;
}

// =====================================================================
// Fused bf16x2-split GEMM.
// MODE 0 (node embed):  write g_node_h; a = y.w0, b = y.w1
// MODE 2 (update):      A = [node_h | g_agg + g_agg_e]; x = node_h + (acc+bias);
//                       LayerNorm+ReLU -> dest; opt a,b dots
// MODE 3 (agg_e):       A = ef_sum [NN,64]; out = acc + indeg[r]*bias -> dest
// =====================================================================
template <int KTOT, int MODE>
__global__ void __launch_bounds__(256, 2)
mma_gemm_kernel(const float* __restrict__ A,
                const __nv_bfloat16* __restrict__ WTH,
                const __nv_bfloat16* __restrict__ WTL,
                const float* __restrict__ bias,
                int M,
                const float* __restrict__ aux,    // MODE0/2: W_top; MODE3: indeg
                const float* __restrict__ lns,
                const float* __restrict__ lnb,
                float* __restrict__ dest,
                int doab)
{
    extern __shared__ float smem[];
    constexpr int NCH = KTOT / 32;
    constexpr int PITCH = 80;
    constexpr int PLANE = 128 * PITCH;
    constexpr int OFF_AH = 0, OFF_AL = PLANE, OFF_BH = 2 * PLANE, OFF_BL = 3 * PLANE;
    constexpr int BUF = 4 * PLANE;

    const int tid   = threadIdx.x;
    const int wid   = tid >> 5;
    const int lane  = tid & 31;
    const int warpM = wid >> 1;
    const int warpN = wid & 1;
    const int lq    = lane >> 2;
    const int lr    = lane & 3;
    const int row0  = blockIdx.x * 128;

    const uint32_t sbase = (uint32_t)__cvta_generic_to_shared(smem);

    float acc[2][8][4];
#pragma unroll
    for (int i = 0; i < 2; i++)
#pragma unroll
        for (int j = 0; j < 8; j++)
#pragma unroll
            for (int q = 0; q < 4; q++) acc[i][j][q] = 0.f;

    float4 va[4];
    auto loadA = [&](int kc) {
#pragma unroll
        for (int l = 0; l < 4; l++) {
            int idx = tid + l * 256;
            int r = idx >> 3;
            int kq = (idx & 7) * 4;
            int grow = row0 + r;
            if (grow >= M) grow = M - 1;
            if (MODE == 2) {
                if (kc < 4) {
                    va[l] = *reinterpret_cast<const float4*>(
                        g_node_h + (size_t)grow * 128 + kc * 32 + kq);
                } else {
                    float4 x = *reinterpret_cast<const float4*>(
                        g_agg + (size_t)grow * 128 + (kc - 4) * 32 + kq);
                    float4 y = *reinterpret_cast<const float4*>(
                        g_agg_e + (size_t)grow * 128 + (kc - 4) * 32 + kq);
                    va[l] = make_float4(x.x + y.x, x.y + y.y, x.z + y.z, x.w + y.w);
                }
            } else {
                va[l] = *reinterpret_cast<const float4*>(
                    A + (size_t)grow * KTOT + kc * 32 + kq);
            }
        }
    };
    auto storeA = [&](int buf) {
        const uint32_t bufo = sbase + buf * BUF;
#pragma unroll
        for (int l = 0; l < 4; l++) {
            int idx = tid + l * 256;
            int r = idx >> 3;
            int kq = (idx & 7) * 4;
            uint32_t off = (uint32_t)(r * PITCH + kq * 2);
            float2 rm0, rm1;
            uint32_t h0 = bf16x2_split(make_float2(va[l].x, va[l].y), rm0);
            uint32_t h1 = bf16x2_split(make_float2(va[l].z, va[l].w), rm1);
            ST_V2(bufo + OFF_AH + off, h0, h1);
            ST_V2(bufo + OFF_AL + off, bf16x2_pack(rm0), bf16x2_pack(rm1));
        }
    };
    auto fillB = [&](int kc, int buf) {
        const uint32_t bufo = sbase + buf * BUF;
#pragma unroll
        for (int l = 0; l < 2; l++) {
            int gr = tid + l * 256;
            int row = gr >> 2;
            int seg = gr & 3;
            uint32_t soff = (uint32_t)(row * PITCH + seg * 16);
            const __nv_bfloat16* sh = WTH + (size_t)row * KTOT + kc * 32 + seg * 8;
            const __nv_bfloat16* sl = WTL + (size_t)row * KTOT + kc * 32 + seg * 8;
            CP_ASYNC16(bufo + OFF_BH + soff, sh);
            CP_ASYNC16(bufo + OFF_BL + soff, sl);
        }
        CP_COMMIT();
    };

    loadA(0);
    fillB(0, 0);
    storeA(0);
    CP_WAIT0();
    __syncthreads();

    const int g   = lane & 15;
    const int hh  = lane >> 4;
    const int q8  = lane & 7;
    const int seg = (lane >> 3) & 3;

    for (int kc = 0; kc < NCH; kc++) {
        const int cur = kc & 1;
        if (kc + 1 < NCH) {
            loadA(kc + 1);
            fillB(kc + 1, cur ^ 1);
        }

        const uint32_t bufo = sbase + cur * BUF;
#pragma unroll
        for (int ks = 0; ks < 2; ks++) {
            uint32_t ah[2][4], al[2][4];
#pragma unroll
            for (int tm = 0; tm < 2; tm++) {
                uint32_t ra = bufo + OFF_AH
                    + (uint32_t)((warpM * 32 + tm * 16 + g) * PITCH + ks * 32 + hh * 16);
                LDSM_X4(ah[tm], ra);
                LDSM_X4(al[tm], ra + (OFF_AL - OFF_AH));
            }
#pragma unroll
            for (int p = 0; p < 4; p++) {
                int n = warpN * 64 + (2 * p + (seg >> 1)) * 8 + q8;
                uint32_t rb = bufo + OFF_BH
                    + (uint32_t)(n * PITCH + ks * 32 + (seg & 1) * 16);
                uint32_t bh[4], bl[4];
                LDSM_X4(bh, rb);
                LDSM_X4(bl, rb + (OFF_BL - OFF_BH));
                MMA_BF16(acc[0][2 * p],     ah[0][0], ah[0][1], ah[0][2], ah[0][3], bh[0], bh[1]);
                MMA_BF16(acc[1][2 * p],     ah[1][0], ah[1][1], ah[1][2], ah[1][3], bh[0], bh[1]);
                MMA_BF16(acc[0][2 * p + 1], ah[0][0], ah[0][1], ah[0][2], ah[0][3], bh[2], bh[3]);
                MMA_BF16(acc[1][2 * p + 1], ah[1][0], ah[1][1], ah[1][2], ah[1][3], bh[2], bh[3]);
                MMA_BF16(acc[0][2 * p],     al[0][0], al[0][1], al[0][2], al[0][3], bh[0], bh[1]);
                MMA_BF16(acc[1][2 * p],     al[1][0], al[1][1], al[1][2], al[1][3], bh[0], bh[1]);
                MMA_BF16(acc[0][2 * p + 1], al[0][0], al[0][1], al[0][2], al[0][3], bh[2], bh[3]);
                MMA_BF16(acc[1][2 * p + 1], al[1][0], al[1][1], al[1][2], al[1][3], bh[2], bh[3]);
                MMA_BF16(acc[0][2 * p],     ah[0][0], ah[0][1], ah[0][2], ah[0][3], bl[0], bl[1]);
                MMA_BF16(acc[1][2 * p],     ah[1][0], ah[1][1], ah[1][2], ah[1][3], bl[0], bl[1]);
                MMA_BF16(acc[0][2 * p + 1], ah[0][0], ah[0][1], ah[0][2], ah[0][3], bl[2], bl[3]);
                MMA_BF16(acc[1][2 * p + 1], ah[1][0], ah[1][1], ah[1][2], ah[1][3], bl[2], bl[3]);
            }
        }
        if (kc + 1 < NCH) storeA(cur ^ 1);
        CP_WAIT0();
        __syncthreads();
    }

    // ---------------- epilogue ----------------
    if (MODE != 3) {
#pragma unroll
        for (int tn = 0; tn < 8; tn++) {
            int col = warpN * 64 + tn * 8 + lr * 2;
            float bx = bias[col], by = bias[col + 1];
#pragma unroll
            for (int tm = 0; tm < 2; tm++) {
                acc[tm][tn][0] += bx; acc[tm][tn][1] += by;
                acc[tm][tn][2] += bx; acc[tm][tn][3] += by;
            }
        }
    }
    int rl[2][2], rg[2][2];
#pragma unroll
    for (int tm = 0; tm < 2; tm++) {
        rl[tm][0] = warpM * 32 + tm * 16 + lq;
        rl[tm][1] = rl[tm][0] + 8;
        rg[tm][0] = row0 + rl[tm][0];
        rg[tm][1] = row0 + rl[tm][1];
    }

    float* red0 = smem;
    float* red1 = smem + 128;

    if (MODE == 0) {
        float pa[2][2] = {{0,0},{0,0}}, pb[2][2] = {{0,0},{0,0}};
#pragma unroll
        for (int tn = 0; tn < 8; tn++) {
            int col = warpN * 64 + tn * 8 + lr * 2;
            float w0x = aux[col], w0y = aux[col + 1];
            float w1x = aux[128 + col], w1y = aux[128 + col + 1];
#pragma unroll
            for (int tm = 0; tm < 2; tm++) {
#pragma unroll
                for (int h = 0; h < 2; h++) {
                    float vx = acc[tm][tn][h * 2], vy = acc[tm][tn][h * 2 + 1];
                    if (rg[tm][h] < M)
                        *reinterpret_cast<float2*>(g_node_h + (size_t)rg[tm][h] * 128 + col)
                            = make_float2(vx, vy);
                    pa[tm][h] += vx * w0x + vy * w0y;
                    pb[tm][h] += vx * w1x + vy * w1y;
                }
            }
        }
        if (tid < 128) { red0[tid] = 0.f; red1[tid] = 0.f; }
        __syncthreads();
#pragma unroll
        for (int tm = 0; tm < 2; tm++)
#pragma unroll
            for (int h = 0; h < 2; h++) {
#pragma unroll
                for (int o = 1; o <= 2; o <<= 1) {
                    pa[tm][h] += __shfl_xor_sync(0xffffffffu, pa[tm][h], o);
                    pb[tm][h] += __shfl_xor_sync(0xffffffffu, pb[tm][h], o);
                }
                if (lr == 0) {
                    atomicAdd(&red0[rl[tm][h]], pa[tm][h]);
                    atomicAdd(&red1[rl[tm][h]], pb[tm][h]);
                }
            }
        __syncthreads();
        if (tid < 128 && row0 + tid < M) {
            g_a[row0 + tid] = red0[tid];
            g_b[row0 + tid] = red1[tid];
        }
    }
    else if (MODE == 3) {
        float ind[2][2];
#pragma unroll
        for (int tm = 0; tm < 2; tm++)
#pragma unroll
            for (int h = 0; h < 2; h++)
                ind[tm][h] = (rg[tm][h] < M) ? aux[rg[tm][h]] : 0.f;
#pragma unroll
        for (int tn = 0; tn < 8; tn++) {
            int col = warpN * 64 + tn * 8 + lr * 2;
            float bx = bias[col], by = bias[col + 1];
#pragma unroll
            for (int tm = 0; tm < 2; tm++) {
#pragma unroll
                for (int h = 0; h < 2; h++) {
                    if (rg[tm][h] < M) {
                        float2 v = make_float2(acc[tm][tn][h * 2] + ind[tm][h] * bx,
                                               acc[tm][tn][h * 2 + 1] + ind[tm][h] * by);
                        *reinterpret_cast<float2*>(dest + (size_t)rg[tm][h] * 128 + col) = v;
                    }
                }
            }
        }
    }
    else {
        float ps[2][2] = {{0,0},{0,0}}, pq[2][2] = {{0,0},{0,0}};
#pragma unroll
        for (int tn = 0; tn < 8; tn++) {
            int col = warpN * 64 + tn * 8 + lr * 2;
#pragma unroll
            for (int tm = 0; tm < 2; tm++) {
#pragma unroll
                for (int h = 0; h < 2; h++) {
                    float2 res = (rg[tm][h] < M)
                        ? *reinterpret_cast<const float2*>(g_node_h + (size_t)rg[tm][h] * 128 + col)
                        : make_float2(0.f, 0.f);
                    float x0 = acc[tm][tn][h * 2] + res.x;
                    float x1 = acc[tm][tn][h * 2 + 1] + res.y;
                    acc[tm][tn][h * 2] = x0;
                    acc[tm][tn][h * 2 + 1] = x1;
                    ps[tm][h] += x0 + x1;
                    pq[tm][h] += x0 * x0 + x1 * x1;
                }
            }
        }
        if (tid < 128) { red0[tid] = 0.f; red1[tid] = 0.f; }
        __syncthreads();
#pragma unroll
        for (int tm = 0; tm < 2; tm++)
#pragma unroll
            for (int h = 0; h < 2; h++) {
#pragma unroll
                for (int o = 1; o <= 2; o <<= 1) {
                    ps[tm][h] += __shfl_xor_sync(0xffffffffu, ps[tm][h], o);
                    pq[tm][h] += __shfl_xor_sync(0xffffffffu, pq[tm][h], o);
                }
                if (lr == 0) {
                    atomicAdd(&red0[rl[tm][h]], ps[tm][h]);
                    atomicAdd(&red1[rl[tm][h]], pq[tm][h]);
                }
            }
        __syncthreads();
        float mean_[2][2], inv_[2][2];
#pragma unroll
        for (int tm = 0; tm < 2; tm++)
#pragma unroll
            for (int h = 0; h < 2; h++) {
                float m = red0[rl[tm][h]] * (1.f / 128.f);
                float var = red1[rl[tm][h]] * (1.f / 128.f) - m * m;
                mean_[tm][h] = m;
                inv_[tm][h] = rsqrtf(fmaxf(var, 0.f) + 1e-6f);
            }
        float pa[2][2] = {{0,0},{0,0}}, pb[2][2] = {{0,0},{0,0}};
#pragma unroll
        for (int tn = 0; tn < 8; tn++) {
            int col = warpN * 64 + tn * 8 + lr * 2;
            float scx = lns[col], scy = lns[col + 1];
            float bix = lnb[col], biy = lnb[col + 1];
            float w0x = aux[col], w0y = aux[col + 1];
            float w1x = aux[128 + col], w1y = aux[128 + col + 1];
#pragma unroll
            for (int tm = 0; tm < 2; tm++) {
#pragma unroll
                for (int h = 0; h < 2; h++) {
                    float y0 = fmaxf(0.f, (acc[tm][tn][h * 2] - mean_[tm][h]) * inv_[tm][h] * scx + bix);
                    float y1 = fmaxf(0.f, (acc[tm][tn][h * 2 + 1] - mean_[tm][h]) * inv_[tm][h] * scy + biy);
                    if (rg[tm][h] < M)
                        *reinterpret_cast<float2*>(dest + (size_t)rg[tm][h] * 128 + col)
                            = make_float2(y0, y1);
                    pa[tm][h] += y0 * w0x + y1 * w0y;
                    pb[tm][h] += y0 * w1x + y1 * w1y;
                }
            }
        }
        if (doab) {
            __syncthreads();
            if (tid < 128) { red0[tid] = 0.f; red1[tid] = 0.f; }
            __syncthreads();
#pragma unroll
            for (int tm = 0; tm < 2; tm++)
#pragma unroll
                for (int h = 0; h < 2; h++) {
#pragma unroll
                    for (int o = 1; o <= 2; o <<= 1) {
                        pa[tm][h] += __shfl_xor_sync(0xffffffffu, pa[tm][h], o);
                        pb[tm][h] += __shfl_xor_sync(0xffffffffu, pb[tm][h], o);
                    }
                    if (lr == 0) {
                        atomicAdd(&red0[rl[tm][h]], pa[tm][h]);
                        atomicAdd(&red1[rl[tm][h]], pb[tm][h]);
                    }
                }
            __syncthreads();
            if (tid < 128 && row0 + tid < M) {
                g_a[row0 + tid] = red0[tid];
                g_b[row0 + tid] = red1[tid];
            }
        }
    }
}

// ---------------- per-layer edge phase: gate + scatter src_f*wgt ----------------
__global__ void __launch_bounds__(256)
edge_kernel(const int* __restrict__ src_idx, const int* __restrict__ dst_idx,
            const float* __restrict__ b_top, float* __restrict__ w_out)
{
    int e = (blockIdx.x * blockDim.x + threadIdx.x) >> 5;
    int lane = threadIdx.x & 31;
    if (e >= NE) return;

    int s = src_idx[e];
    int d = dst_idx[e];

    float wgt;
    if (lane == 0) {
        float g = g_a[s] + g_b[d] + g_edot[e] + b_top[0];
        wgt = 1.f / (1.f + __expf(-g));
    }
    wgt = __shfl_sync(0xffffffffu, wgt, 0);

    float4 sv = *reinterpret_cast<const float4*>(g_node_h + (size_t)s * 128 + lane * 4);
    float4 msg = make_float4(sv.x * wgt, sv.y * wgt, sv.z * wgt, sv.w * wgt);
    atomicAdd(reinterpret_cast<float4*>(g_agg + (size_t)d * 128 + lane * 4), msg);

    if (w_out != nullptr && lane == 0) w_out[e] = wgt;
}

// ---------------- launch ----------------
extern "C" void kernel_launch(void* const* d_in, const int* in_sizes, int n_in,
                              void* d_out, int out_size)
{
    const float* nf     = (const float*)d_in[0];
    const float* ef     = (const float*)d_in[1];
    const int*   ei     = (const int*)  d_in[2];
    const float* W_node = (const float*)d_in[3];
    const float* b_node = (const float*)d_in[4];
    const float* W_edge = (const float*)d_in[5];
    const float* b_edge = (const float*)d_in[6];
    const float* W_gnn  = (const float*)d_in[7];
    const float* b_gnn  = (const float*)d_in[8];
    const float* W_top  = (const float*)d_in[9];
    const float* b_top  = (const float*)d_in[10];
    const float* ln_s   = (const float*)d_in[11];
    const float* ln_b   = (const float*)d_in[12];

    float* out       = (float*)d_out;
    float* out_nodes = out;
    float* out_w     = out + (size_t)NN * 128;

    const int* src = ei;
    const int* dst = ei + NE;

    const int SMEM_SZ = 2 * 4 * 128 * 80;   // 81920 B
    cudaFuncSetAttribute(mma_gemm_kernel<128, 0>, cudaFuncAttributeMaxDynamicSharedMemorySize, SMEM_SZ);
    cudaFuncSetAttribute(mma_gemm_kernel<64, 3>,  cudaFuncAttributeMaxDynamicSharedMemorySize, SMEM_SZ);
    cudaFuncSetAttribute(mma_gemm_kernel<256, 2>, cudaFuncAttributeMaxDynamicSharedMemorySize, SMEM_SZ);

    __nv_bfloat16 *wthn = nullptr, *wtln = nullptr, *wthe = nullptr, *wtle = nullptr;
    __nv_bfloat16 *wthg = nullptr, *wtlg = nullptr;
    cudaGetSymbolAddress((void**)&wthn, g_wth_node);
    cudaGetSymbolAddress((void**)&wtln, g_wtl_node);
    cudaGetSymbolAddress((void**)&wthe, g_wth_edge);
    cudaGetSymbolAddress((void**)&wtle, g_wtl_edge);
    cudaGetSymbolAddress((void**)&wthg, g_wth_gnn);
    cudaGetSymbolAddress((void**)&wtlg, g_wtl_gnn);
    float* nodeh = nullptr; float* aggep = nullptr;
    float* efsum = nullptr; float* indeg = nullptr; float* aggp = nullptr;
    cudaGetSymbolAddress((void**)&nodeh, g_node_h);
    cudaGetSymbolAddress((void**)&aggep, g_agg_e);
    cudaGetSymbolAddress((void**)&efsum, g_ef_sum);
    cudaGetSymbolAddress((void**)&indeg, g_indeg);
    cudaGetSymbolAddress((void**)&aggp, g_agg);

    // second stream + events for fork-join (created once; graph-capture legal)
    static cudaStream_t s2 = nullptr;
    static cudaEvent_t ev_fork = nullptr, ev_join = nullptr;
    if (s2 == nullptr) {
        cudaStreamCreateWithFlags(&s2, cudaStreamNonBlocking);
        cudaEventCreateWithFlags(&ev_fork, cudaEventDisableTiming);
        cudaEventCreateWithFlags(&ev_join, cudaEventDisableTiming);
    }

    // fused prologue (zeros + transposes + ve) on main stream
    prep_kernel<<<(PREP_TOTAL + 255) / 256, 256>>>(W_node, W_edge, W_gnn, b_edge, W_top);

    // fork: node embed on s2 (independent of edge chain)
    cudaEventRecord(ev_fork, 0);
    cudaStreamWaitEvent(s2, ev_fork, 0);
    mma_gemm_kernel<128, 0><<<(NN + 127) / 128, 256, SMEM_SZ, s2>>>(
        nf, wthn, wtln, b_node, NN, W_top, nullptr, nullptr, nullptr, 0);
    cudaEventRecord(ev_join, s2);

    // main stream: edge feature sum + edot, then agg_e GEMM
    edge_sum_kernel<<<(NE * 16 + 255) / 256, 256>>>(ef, dst);
    mma_gemm_kernel<64, 3><<<(NN + 127) / 128, 256, SMEM_SZ>>>(
        efsum, wthe, wtle, b_edge, NN, indeg, nullptr, nullptr, aggep, 0);

    // join: layer loop needs node_h/a/b from s2
    cudaStreamWaitEvent(0, ev_join, 0);

    for (int i = 0; i < 3; i++) {
        zero_buf_kernel<<<1024, 256>>>(aggp, NN * 128 / 4);
        edge_kernel<<<(NE * 32 + 255) / 256, 256>>>(
            src, dst, b_top, (i == 2) ? out_w : nullptr);
        mma_gemm_kernel<256, 2><<<(NN + 127) / 128, 256, SMEM_SZ>>>(
            nullptr, wthg + (size_t)i * 128 * 256, wtlg + (size_t)i * 128 * 256,
            b_gnn + i * 128, NN,
            W_top, ln_s + i * 128, ln_b + i * 128,
            (i == 2) ? out_nodes : nodeh, (i < 2) ? 1 : 0);
    }
}

// round 14
// speedup vs baseline: 1.0897x; 1.0452x over previous
#include <cuda_runtime.h>
#include <cuda_bf16.h>
#include <math.h>
#include <stdint.h>

#define NN 50000
#define NE 200000

// ---------------- scratch (device globals; no allocation) ----------------
__device__ float g_node_h[(size_t)NN * 128];
__device__ float g_agg[(size_t)NN * 128];     // per-layer scatter target
__device__ float g_agg_e[(size_t)NN * 128];   // layer-invariant: sum of edge_h into dst
__device__ float g_ef_sum[(size_t)NN * 64];   // sum of raw edge features into dst
__device__ float g_indeg[NN];
__device__ float g_a[NN];                     // node_h . w0
__device__ float g_b[NN];                     // node_h . w1
__device__ float g_edot[NE];                  // edge_h . w2 (layer-invariant)
__device__ float g_ve[64];                    // W_edge @ w2
__device__ float g_vc;                        // b_edge . w2
// pre-split bf16 weight planes, [n][k] layout (B operand, col-major)
__device__ __nv_bfloat16 g_wth_node[128 * 128], g_wtl_node[128 * 128];
__device__ __nv_bfloat16 g_wth_edge[128 * 64],  g_wtl_edge[128 * 64];
__device__ __nv_bfloat16 g_wth_gnn[3 * 128 * 256], g_wtl_gnn[3 * 128 * 256];

__device__ __forceinline__ void split_store(float x, __nv_bfloat16* ph, __nv_bfloat16* pl) {
    __nv_bfloat16 h = __float2bfloat16(x);
    *ph = h;
    *pl = __float2bfloat16(x - __bfloat162float(h));
}

// ---------------- fused prologue: zeros + transposes + ve ----------------
// flat index space:
//  [0, 1600000)             zero g_agg (float4; NN*128/4)
//  [1600000, 2400000)       zero g_ef_sum (float4; NN*64/4)
//  [2400000, 2412500)       zero g_indeg (float4)
//  [2412500, 2428884)       transpose+split W_node (16384)
//  [2428884, 2437076)       transpose+split W_edge (8192)
//  [2437076, 2535380)       transpose+split W_gnn (98304)
//  [2535380, 2535444)       ve (64)
#define PREP_TOTAL 2535444
__global__ void prep_kernel(const float* __restrict__ W_node,
                            const float* __restrict__ W_edge,
                            const float* __restrict__ W_gnn,
                            const float* __restrict__ b_edge,
                            const float* __restrict__ W_top)
{
    int i = blockIdx.x * blockDim.x + threadIdx.x;
    if (i < 1600000) {
        reinterpret_cast<float4*>(g_agg)[i] = make_float4(0.f, 0.f, 0.f, 0.f);
    } else if (i < 2400000) {
        reinterpret_cast<float4*>(g_ef_sum)[i - 1600000] = make_float4(0.f, 0.f, 0.f, 0.f);
    } else if (i < 2412500) {
        reinterpret_cast<float4*>(g_indeg)[i - 2400000] = make_float4(0.f, 0.f, 0.f, 0.f);
    } else if (i < 2428884) {
        int j = i - 2412500;
        int k = j >> 7, n = j & 127;
        split_store(W_node[j], &g_wth_node[n * 128 + k], &g_wtl_node[n * 128 + k]);
    } else if (i < 2437076) {
        int j = i - 2428884;
        int k = j >> 7, n = j & 127;
        split_store(W_edge[j], &g_wth_edge[n * 64 + k], &g_wtl_edge[n * 64 + k]);
    } else if (i < 2535380) {
        int j = i - 2437076;
        int l = j / 32768, r = j % 32768;
        int k = r >> 7, n = r & 127;
        split_store(W_gnn[j], &g_wth_gnn[l * 32768 + n * 256 + k],
                              &g_wtl_gnn[l * 32768 + n * 256 + k]);
    } else if (i < 2535444) {
        int k = i - 2535380;
        float s = 0.f;
        for (int n = 0; n < 128; n++) s += W_edge[k * 128 + n] * W_top[256 + n];
        g_ve[k] = s;
        if (k == 0) {
            float c = 0.f;
            for (int n = 0; n < 128; n++) c += b_edge[n] * W_top[256 + n];
            g_vc = c;
        }
    }
}

// ---------------- edge feature sum + edot (16 lanes per edge) ----------------
__global__ void __launch_bounds__(256)
edge_sum_kernel(const float* __restrict__ ef, const int* __restrict__ dst_idx)
{
    int t = blockIdx.x * blockDim.x + threadIdx.x;
    int e = t >> 4;
    int l = t & 15;
    if (e >= NE) return;

    float4 v  = *reinterpret_cast<const float4*>(ef + (size_t)e * 64 + l * 4);
    float4 ve = *reinterpret_cast<const float4*>(g_ve + l * 4);
    float p = v.x * ve.x + v.y * ve.y + v.z * ve.z + v.w * ve.w;
#pragma unroll
    for (int o = 1; o < 16; o <<= 1) p += __shfl_xor_sync(0xffffffffu, p, o);

    int d = dst_idx[e];
    if (l == 0) {
        g_edot[e] = p + g_vc;
        atomicAdd(&g_indeg[d], 1.f);
    }
    atomicAdd(reinterpret_cast<float4*>(g_ef_sum + (size_t)d * 64 + l * 4), v);
}

// ---------------- mma / ldmatrix / cp.async / bf16 helpers ----------------
#define MMA_BF16(d, a0, a1, a2, a3, b0, b1)                                    \
    asm volatile(                                                              \
        "mma.sync.aligned.m16n8k16.row.col.f32.bf16.bf16.f32 "                 \
        "{%0,%1,%2,%3}, {%4,%5,%6,%7}, {%8,%9}, {%0,%1,%2,%3};"                \
        : "+f"((d)[0]), "+f"((d)[1]), "+f"((d)[2]), "+f"((d)[3])               \
        : "r"(a0), "r"(a1), "r"(a2), "r"(a3), "r"(b0), "r"(b1))

#define LDSM_X4(R, addr)                                                       \
    asm volatile("ldmatrix.sync.aligned.m8n8.x4.shared.b16 {%0,%1,%2,%3}, [%4];" \
        : "=r"((R)[0]), "=r"((R)[1]), "=r"((R)[2]), "=r"((R)[3]) : "r"(addr))

#define ST_V2(addr, x, y)                                                      \
    asm volatile("st.shared.v2.u32 [%0], {%1,%2};" :: "r"(addr), "r"(x), "r"(y))

#define CP_ASYNC16(saddr, gptr) \
    asm volatile("cp.async.cg.shared.global [%0], [%1], 16;" :: "r"(saddr), "l"(gptr))
#define CP_COMMIT() asm volatile("cp.async.commit_group;")
#define CP_WAIT0()  asm volatile("cp.async.wait_group 0;")

__device__ __forceinline__ uint32_t bf16x2_split(float2 f, float2& rem) {
    uint32_t h;
    asm("cvt.rn.bf16x2.f32 %0, %1, %2;" : "=r"(h) : "f"(f.y), "f"(f.x));
    float hx = __uint_as_float(h << 16);
    float hy = __uint_as_float(h & 0xFFFF0000u);
    rem.x = f.x - hx;
    rem.y = f.y - hy;
    return h;
}
__device__ __forceinline__ uint32_t bf16x2_pack(float2 f) {
    uint32_t h;
    asm("cvt.rn.bf16x2.f32 %0, %1, %2;" : "=r"(h) : "f"(f.y), "f"(f.x));
    return h;
}

// =====================================================================
// Fused bf16x2-split GEMM.
// MODE 0 (node embed):  write g_node_h; a = y.w0, b = y.w1
// MODE 2 (update):      A = [node_h | g_agg + g_agg_e]; x = node_h + (acc+bias);
//                       LayerNorm+ReLU -> dest; if doab: a,b dots AND re-zero
//                       this CTA's g_agg rows for the next layer
// MODE 3 (agg_e):       A = ef_sum [NN,64]; out = acc + indeg[r]*bias -> dest
// =====================================================================
template <int KTOT, int MODE>
__global__ void __launch_bounds__(256, 2)
mma_gemm_kernel(const float* __restrict__ A,
                const __nv_bfloat16* __restrict__ WTH,
                const __nv_bfloat16* __restrict__ WTL,
                const float* __restrict__ bias,
                int M,
                const float* __restrict__ aux,    // MODE0/2: W_top; MODE3: indeg
                const float* __restrict__ lns,
                const float* __restrict__ lnb,
                float* __restrict__ dest,
                int doab)
{
    extern __shared__ float smem[];
    constexpr int NCH = KTOT / 32;
    constexpr int PITCH = 80;
    constexpr int PLANE = 128 * PITCH;
    constexpr int OFF_AH = 0, OFF_AL = PLANE, OFF_BH = 2 * PLANE, OFF_BL = 3 * PLANE;
    constexpr int BUF = 4 * PLANE;

    const int tid   = threadIdx.x;
    const int wid   = tid >> 5;
    const int lane  = tid & 31;
    const int warpM = wid >> 1;
    const int warpN = wid & 1;
    const int lq    = lane >> 2;
    const int lr    = lane & 3;
    const int row0  = blockIdx.x * 128;

    const uint32_t sbase = (uint32_t)__cvta_generic_to_shared(smem);

    float acc[2][8][4];
#pragma unroll
    for (int i = 0; i < 2; i++)
#pragma unroll
        for (int j = 0; j < 8; j++)
#pragma unroll
            for (int q = 0; q < 4; q++) acc[i][j][q] = 0.f;

    float4 va[4];
    auto loadA = [&](int kc) {
#pragma unroll
        for (int l = 0; l < 4; l++) {
            int idx = tid + l * 256;
            int r = idx >> 3;
            int kq = (idx & 7) * 4;
            int grow = row0 + r;
            if (grow >= M) grow = M - 1;
            if (MODE == 2) {
                if (kc < 4) {
                    va[l] = *reinterpret_cast<const float4*>(
                        g_node_h + (size_t)grow * 128 + kc * 32 + kq);
                } else {
                    float4 x = *reinterpret_cast<const float4*>(
                        g_agg + (size_t)grow * 128 + (kc - 4) * 32 + kq);
                    float4 y = *reinterpret_cast<const float4*>(
                        g_agg_e + (size_t)grow * 128 + (kc - 4) * 32 + kq);
                    va[l] = make_float4(x.x + y.x, x.y + y.y, x.z + y.z, x.w + y.w);
                }
            } else {
                va[l] = *reinterpret_cast<const float4*>(
                    A + (size_t)grow * KTOT + kc * 32 + kq);
            }
        }
    };
    auto storeA = [&](int buf) {
        const uint32_t bufo = sbase + buf * BUF;
#pragma unroll
        for (int l = 0; l < 4; l++) {
            int idx = tid + l * 256;
            int r = idx >> 3;
            int kq = (idx & 7) * 4;
            uint32_t off = (uint32_t)(r * PITCH + kq * 2);
            float2 rm0, rm1;
            uint32_t h0 = bf16x2_split(make_float2(va[l].x, va[l].y), rm0);
            uint32_t h1 = bf16x2_split(make_float2(va[l].z, va[l].w), rm1);
            ST_V2(bufo + OFF_AH + off, h0, h1);
            ST_V2(bufo + OFF_AL + off, bf16x2_pack(rm0), bf16x2_pack(rm1));
        }
    };
    auto fillB = [&](int kc, int buf) {
        const uint32_t bufo = sbase + buf * BUF;
#pragma unroll
        for (int l = 0; l < 2; l++) {
            int gr = tid + l * 256;
            int row = gr >> 2;
            int seg = gr & 3;
            uint32_t soff = (uint32_t)(row * PITCH + seg * 16);
            const __nv_bfloat16* sh = WTH + (size_t)row * KTOT + kc * 32 + seg * 8;
            const __nv_bfloat16* sl = WTL + (size_t)row * KTOT + kc * 32 + seg * 8;
            CP_ASYNC16(bufo + OFF_BH + soff, sh);
            CP_ASYNC16(bufo + OFF_BL + soff, sl);
        }
        CP_COMMIT();
    };

    loadA(0);
    fillB(0, 0);
    storeA(0);
    CP_WAIT0();
    __syncthreads();

    const int g   = lane & 15;
    const int hh  = lane >> 4;
    const int q8  = lane & 7;
    const int seg = (lane >> 3) & 3;

    for (int kc = 0; kc < NCH; kc++) {
        const int cur = kc & 1;
        if (kc + 1 < NCH) {
            loadA(kc + 1);
            fillB(kc + 1, cur ^ 1);
        }

        const uint32_t bufo = sbase + cur * BUF;
#pragma unroll
        for (int ks = 0; ks < 2; ks++) {
            uint32_t ah[2][4], al[2][4];
#pragma unroll
            for (int tm = 0; tm < 2; tm++) {
                uint32_t ra = bufo + OFF_AH
                    + (uint32_t)((warpM * 32 + tm * 16 + g) * PITCH + ks * 32 + hh * 16);
                LDSM_X4(ah[tm], ra);
                LDSM_X4(al[tm], ra + (OFF_AL - OFF_AH));
            }
#pragma unroll
            for (int p = 0; p < 4; p++) {
                int n = warpN * 64 + (2 * p + (seg >> 1)) * 8 + q8;
                uint32_t rb = bufo + OFF_BH
                    + (uint32_t)(n * PITCH + ks * 32 + (seg & 1) * 16);
                uint32_t bh[4], bl[4];
                LDSM_X4(bh, rb);
                LDSM_X4(bl, rb + (OFF_BL - OFF_BH));
                MMA_BF16(acc[0][2 * p],     ah[0][0], ah[0][1], ah[0][2], ah[0][3], bh[0], bh[1]);
                MMA_BF16(acc[1][2 * p],     ah[1][0], ah[1][1], ah[1][2], ah[1][3], bh[0], bh[1]);
                MMA_BF16(acc[0][2 * p + 1], ah[0][0], ah[0][1], ah[0][2], ah[0][3], bh[2], bh[3]);
                MMA_BF16(acc[1][2 * p + 1], ah[1][0], ah[1][1], ah[1][2], ah[1][3], bh[2], bh[3]);
                MMA_BF16(acc[0][2 * p],     al[0][0], al[0][1], al[0][2], al[0][3], bh[0], bh[1]);
                MMA_BF16(acc[1][2 * p],     al[1][0], al[1][1], al[1][2], al[1][3], bh[0], bh[1]);
                MMA_BF16(acc[0][2 * p + 1], al[0][0], al[0][1], al[0][2], al[0][3], bh[2], bh[3]);
                MMA_BF16(acc[1][2 * p + 1], al[1][0], al[1][1], al[1][2], al[1][3], bh[2], bh[3]);
                MMA_BF16(acc[0][2 * p],     ah[0][0], ah[0][1], ah[0][2], ah[0][3], bl[0], bl[1]);
                MMA_BF16(acc[1][2 * p],     ah[1][0], ah[1][1], ah[1][2], ah[1][3], bl[0], bl[1]);
                MMA_BF16(acc[0][2 * p + 1], ah[0][0], ah[0][1], ah[0][2], ah[0][3], bl[2], bl[3]);
                MMA_BF16(acc[1][2 * p + 1], ah[1][0], ah[1][1], ah[1][2], ah[1][3], bl[2], bl[3]);
            }
        }
        if (kc + 1 < NCH) storeA(cur ^ 1);
        CP_WAIT0();
        __syncthreads();
    }

    // ---------------- epilogue ----------------
    if (MODE != 3) {
#pragma unroll
        for (int tn = 0; tn < 8; tn++) {
            int col = warpN * 64 + tn * 8 + lr * 2;
            float bx = bias[col], by = bias[col + 1];
#pragma unroll
            for (int tm = 0; tm < 2; tm++) {
                acc[tm][tn][0] += bx; acc[tm][tn][1] += by;
                acc[tm][tn][2] += bx; acc[tm][tn][3] += by;
            }
        }
    }
    int rl[2][2], rg[2][2];
#pragma unroll
    for (int tm = 0; tm < 2; tm++) {
        rl[tm][0] = warpM * 32 + tm * 16 + lq;
        rl[tm][1] = rl[tm][0] + 8;
        rg[tm][0] = row0 + rl[tm][0];
        rg[tm][1] = row0 + rl[tm][1];
    }

    float* red0 = smem;
    float* red1 = smem + 128;

    if (MODE == 0) {
        float pa[2][2] = {{0,0},{0,0}}, pb[2][2] = {{0,0},{0,0}};
#pragma unroll
        for (int tn = 0; tn < 8; tn++) {
            int col = warpN * 64 + tn * 8 + lr * 2;
            float w0x = aux[col], w0y = aux[col + 1];
            float w1x = aux[128 + col], w1y = aux[128 + col + 1];
#pragma unroll
            for (int tm = 0; tm < 2; tm++) {
#pragma unroll
                for (int h = 0; h < 2; h++) {
                    float vx = acc[tm][tn][h * 2], vy = acc[tm][tn][h * 2 + 1];
                    if (rg[tm][h] < M)
                        *reinterpret_cast<float2*>(g_node_h + (size_t)rg[tm][h] * 128 + col)
                            = make_float2(vx, vy);
                    pa[tm][h] += vx * w0x + vy * w0y;
                    pb[tm][h] += vx * w1x + vy * w1y;
                }
            }
        }
        if (tid < 128) { red0[tid] = 0.f; red1[tid] = 0.f; }
        __syncthreads();
#pragma unroll
        for (int tm = 0; tm < 2; tm++)
#pragma unroll
            for (int h = 0; h < 2; h++) {
#pragma unroll
                for (int o = 1; o <= 2; o <<= 1) {
                    pa[tm][h] += __shfl_xor_sync(0xffffffffu, pa[tm][h], o);
                    pb[tm][h] += __shfl_xor_sync(0xffffffffu, pb[tm][h], o);
                }
                if (lr == 0) {
                    atomicAdd(&red0[rl[tm][h]], pa[tm][h]);
                    atomicAdd(&red1[rl[tm][h]], pb[tm][h]);
                }
            }
        __syncthreads();
        if (tid < 128 && row0 + tid < M) {
            g_a[row0 + tid] = red0[tid];
            g_b[row0 + tid] = red1[tid];
        }
    }
    else if (MODE == 3) {
        float ind[2][2];
#pragma unroll
        for (int tm = 0; tm < 2; tm++)
#pragma unroll
            for (int h = 0; h < 2; h++)
                ind[tm][h] = (rg[tm][h] < M) ? aux[rg[tm][h]] : 0.f;
#pragma unroll
        for (int tn = 0; tn < 8; tn++) {
            int col = warpN * 64 + tn * 8 + lr * 2;
            float bx = bias[col], by = bias[col + 1];
#pragma unroll
            for (int tm = 0; tm < 2; tm++) {
#pragma unroll
                for (int h = 0; h < 2; h++) {
                    if (rg[tm][h] < M) {
                        float2 v = make_float2(acc[tm][tn][h * 2] + ind[tm][h] * bx,
                                               acc[tm][tn][h * 2 + 1] + ind[tm][h] * by);
                        *reinterpret_cast<float2*>(dest + (size_t)rg[tm][h] * 128 + col) = v;
                    }
                }
            }
        }
    }
    else {
        float ps[2][2] = {{0,0},{0,0}}, pq[2][2] = {{0,0},{0,0}};
#pragma unroll
        for (int tn = 0; tn < 8; tn++) {
            int col = warpN * 64 + tn * 8 + lr * 2;
#pragma unroll
            for (int tm = 0; tm < 2; tm++) {
#pragma unroll
                for (int h = 0; h < 2; h++) {
                    float2 res = (rg[tm][h] < M)
                        ? *reinterpret_cast<const float2*>(g_node_h + (size_t)rg[tm][h] * 128 + col)
                        : make_float2(0.f, 0.f);
                    float x0 = acc[tm][tn][h * 2] + res.x;
                    float x1 = acc[tm][tn][h * 2 + 1] + res.y;
                    acc[tm][tn][h * 2] = x0;
                    acc[tm][tn][h * 2 + 1] = x1;
                    ps[tm][h] += x0 + x1;
                    pq[tm][h] += x0 * x0 + x1 * x1;
                }
            }
        }
        if (tid < 128) { red0[tid] = 0.f; red1[tid] = 0.f; }
        __syncthreads();
#pragma unroll
        for (int tm = 0; tm < 2; tm++)
#pragma unroll
            for (int h = 0; h < 2; h++) {
#pragma unroll
                for (int o = 1; o <= 2; o <<= 1) {
                    ps[tm][h] += __shfl_xor_sync(0xffffffffu, ps[tm][h], o);
                    pq[tm][h] += __shfl_xor_sync(0xffffffffu, pq[tm][h], o);
                }
                if (lr == 0) {
                    atomicAdd(&red0[rl[tm][h]], ps[tm][h]);
                    atomicAdd(&red1[rl[tm][h]], pq[tm][h]);
                }
            }
        __syncthreads();
        float mean_[2][2], inv_[2][2];
#pragma unroll
        for (int tm = 0; tm < 2; tm++)
#pragma unroll
            for (int h = 0; h < 2; h++) {
                float m = red0[rl[tm][h]] * (1.f / 128.f);
                float var = red1[rl[tm][h]] * (1.f / 128.f) - m * m;
                mean_[tm][h] = m;
                inv_[tm][h] = rsqrtf(fmaxf(var, 0.f) + 1e-6f);
            }
        float pa[2][2] = {{0,0},{0,0}}, pb[2][2] = {{0,0},{0,0}};
#pragma unroll
        for (int tn = 0; tn < 8; tn++) {
            int col = warpN * 64 + tn * 8 + lr * 2;
            float scx = lns[col], scy = lns[col + 1];
            float bix = lnb[col], biy = lnb[col + 1];
            float w0x = aux[col], w0y = aux[col + 1];
            float w1x = aux[128 + col], w1y = aux[128 + col + 1];
#pragma unroll
            for (int tm = 0; tm < 2; tm++) {
#pragma unroll
                for (int h = 0; h < 2; h++) {
                    float y0 = fmaxf(0.f, (acc[tm][tn][h * 2] - mean_[tm][h]) * inv_[tm][h] * scx + bix);
                    float y1 = fmaxf(0.f, (acc[tm][tn][h * 2 + 1] - mean_[tm][h]) * inv_[tm][h] * scy + biy);
                    if (rg[tm][h] < M)
                        *reinterpret_cast<float2*>(dest + (size_t)rg[tm][h] * 128 + col)
                            = make_float2(y0, y1);
                    pa[tm][h] += y0 * w0x + y1 * w0y;
                    pb[tm][h] += y0 * w1x + y1 * w1y;
                }
            }
        }
        if (doab) {
            __syncthreads();
            if (tid < 128) { red0[tid] = 0.f; red1[tid] = 0.f; }
            __syncthreads();
#pragma unroll
            for (int tm = 0; tm < 2; tm++)
#pragma unroll
                for (int h = 0; h < 2; h++) {
#pragma unroll
                    for (int o = 1; o <= 2; o <<= 1) {
                        pa[tm][h] += __shfl_xor_sync(0xffffffffu, pa[tm][h], o);
                        pb[tm][h] += __shfl_xor_sync(0xffffffffu, pb[tm][h], o);
                    }
                    if (lr == 0) {
                        atomicAdd(&red0[rl[tm][h]], pa[tm][h]);
                        atomicAdd(&red1[rl[tm][h]], pb[tm][h]);
                    }
                }
            __syncthreads();
            if (tid < 128 && row0 + tid < M) {
                g_a[row0 + tid] = red0[tid];
                g_b[row0 + tid] = red1[tid];
            }
            // re-zero this CTA's g_agg rows for the next layer's scatter
            // (this CTA was the only reader of these rows; write-after-read safe)
            float4 z = make_float4(0.f, 0.f, 0.f, 0.f);
#pragma unroll
            for (int c = 0; c < 4; c++) {
#pragma unroll
                for (int l = 0; l < 4; l++) {
                    int idx = tid + l * 256;
                    int r = idx >> 3;
                    int kq = (idx & 7) * 4;
                    int grow = row0 + r;
                    if (grow < M)
                        *reinterpret_cast<float4*>(
                            g_agg + (size_t)grow * 128 + c * 32 + kq) = z;
                }
            }
        }
    }
}

// ---------------- per-layer edge phase: gate + scatter src_f*wgt ----------------
__global__ void __launch_bounds__(256)
edge_kernel(const int* __restrict__ src_idx, const int* __restrict__ dst_idx,
            const float* __restrict__ b_top, float* __restrict__ w_out)
{
    int e = (blockIdx.x * blockDim.x + threadIdx.x) >> 5;
    int lane = threadIdx.x & 31;
    if (e >= NE) return;

    int s = src_idx[e];
    int d = dst_idx[e];

    float wgt;
    if (lane == 0) {
        float g = g_a[s] + g_b[d] + g_edot[e] + b_top[0];
        wgt = 1.f / (1.f + __expf(-g));
    }
    wgt = __shfl_sync(0xffffffffu, wgt, 0);

    float4 sv = *reinterpret_cast<const float4*>(g_node_h + (size_t)s * 128 + lane * 4);
    float4 msg = make_float4(sv.x * wgt, sv.y * wgt, sv.z * wgt, sv.w * wgt);
    atomicAdd(reinterpret_cast<float4*>(g_agg + (size_t)d * 128 + lane * 4), msg);

    if (w_out != nullptr && lane == 0) w_out[e] = wgt;
}

// ---------------- launch ----------------
extern "C" void kernel_launch(void* const* d_in, const int* in_sizes, int n_in,
                              void* d_out, int out_size)
{
    const float* nf     = (const float*)d_in[0];
    const float* ef     = (const float*)d_in[1];
    const int*   ei     = (const int*)  d_in[2];
    const float* W_node = (const float*)d_in[3];
    const float* b_node = (const float*)d_in[4];
    const float* W_edge = (const float*)d_in[5];
    const float* b_edge = (const float*)d_in[6];
    const float* W_gnn  = (const float*)d_in[7];
    const float* b_gnn  = (const float*)d_in[8];
    const float* W_top  = (const float*)d_in[9];
    const float* b_top  = (const float*)d_in[10];
    const float* ln_s   = (const float*)d_in[11];
    const float* ln_b   = (const float*)d_in[12];

    float* out       = (float*)d_out;
    float* out_nodes = out;
    float* out_w     = out + (size_t)NN * 128;

    const int* src = ei;
    const int* dst = ei + NE;

    const int SMEM_SZ = 2 * 4 * 128 * 80;   // 81920 B
    cudaFuncSetAttribute(mma_gemm_kernel<128, 0>, cudaFuncAttributeMaxDynamicSharedMemorySize, SMEM_SZ);
    cudaFuncSetAttribute(mma_gemm_kernel<64, 3>,  cudaFuncAttributeMaxDynamicSharedMemorySize, SMEM_SZ);
    cudaFuncSetAttribute(mma_gemm_kernel<256, 2>, cudaFuncAttributeMaxDynamicSharedMemorySize, SMEM_SZ);

    __nv_bfloat16 *wthn = nullptr, *wtln = nullptr, *wthe = nullptr, *wtle = nullptr;
    __nv_bfloat16 *wthg = nullptr, *wtlg = nullptr;
    cudaGetSymbolAddress((void**)&wthn, g_wth_node);
    cudaGetSymbolAddress((void**)&wtln, g_wtl_node);
    cudaGetSymbolAddress((void**)&wthe, g_wth_edge);
    cudaGetSymbolAddress((void**)&wtle, g_wtl_edge);
    cudaGetSymbolAddress((void**)&wthg, g_wth_gnn);
    cudaGetSymbolAddress((void**)&wtlg, g_wtl_gnn);
    float* nodeh = nullptr; float* aggep = nullptr;
    float* efsum = nullptr; float* indeg = nullptr;
    cudaGetSymbolAddress((void**)&nodeh, g_node_h);
    cudaGetSymbolAddress((void**)&aggep, g_agg_e);
    cudaGetSymbolAddress((void**)&efsum, g_ef_sum);
    cudaGetSymbolAddress((void**)&indeg, g_indeg);

    // second stream + events for fork-join (created once; graph-capture legal)
    static cudaStream_t s2 = nullptr;
    static cudaEvent_t ev_fork = nullptr, ev_join = nullptr;
    if (s2 == nullptr) {
        cudaStreamCreateWithFlags(&s2, cudaStreamNonBlocking);
        cudaEventCreateWithFlags(&ev_fork, cudaEventDisableTiming);
        cudaEventCreateWithFlags(&ev_join, cudaEventDisableTiming);
    }

    // fused prologue (zeros incl. g_agg + transposes + ve)
    prep_kernel<<<(PREP_TOTAL + 255) / 256, 256>>>(W_node, W_edge, W_gnn, b_edge, W_top);

    // fork: node embed on s2 (independent of edge chain)
    cudaEventRecord(ev_fork, 0);
    cudaStreamWaitEvent(s2, ev_fork, 0);
    mma_gemm_kernel<128, 0><<<(NN + 127) / 128, 256, SMEM_SZ, s2>>>(
        nf, wthn, wtln, b_node, NN, W_top, nullptr, nullptr, nullptr, 0);
    cudaEventRecord(ev_join, s2);

    // main stream: edge feature sum + edot, then agg_e GEMM
    edge_sum_kernel<<<(NE * 16 + 255) / 256, 256>>>(ef, dst);
    mma_gemm_kernel<64, 3><<<(NN + 127) / 128, 256, SMEM_SZ>>>(
        efsum, wthe, wtle, b_edge, NN, indeg, nullptr, nullptr, aggep, 0);

    // join: layer loop needs node_h/a/b from s2
    cudaStreamWaitEvent(0, ev_join, 0);

    for (int i = 0; i < 3; i++) {
        edge_kernel<<<(NE * 32 + 255) / 256, 256>>>(
            src, dst, b_top, (i == 2) ? out_w : nullptr);
        // doab==1 for i<2 also triggers g_agg re-zero for the next layer
        mma_gemm_kernel<256, 2><<<(NN + 127) / 128, 256, SMEM_SZ>>>(
            nullptr, wthg + (size_t)i * 128 * 256, wtlg + (size_t)i * 128 * 256,
            b_gnn + i * 128, NN,
            W_top, ln_s + i * 128, ln_b + i * 128,
            (i == 2) ? out_nodes : nodeh, (i < 2) ? 1 : 0);
    }
}

// round 15
// speedup vs baseline: 1.1040x; 1.0131x over previous
#include <cuda_runtime.h>
#include <cuda_bf16.h>
#include <math.h>
#include <stdint.h>

#define NN 50000
#define NE 200000

// ---------------- scratch (device globals; no allocation) ----------------
__device__ float g_node_h[(size_t)NN * 128];
__device__ float g_agg[(size_t)NN * 128];     // per-layer scatter target
__device__ float g_agg_e[(size_t)NN * 128];   // layer-invariant: sum of edge_h into dst
__device__ float g_ef_sum[(size_t)NN * 64];   // sum of raw edge features into dst
__device__ float g_indeg[NN];
__device__ float g_a[NN];                     // node_h . w0
__device__ float g_b[NN];                     // node_h . w1
__device__ float g_edot[NE];                  // edge_h . w2 (layer-invariant)
__device__ float g_ve[64];                    // W_edge @ w2
__device__ float g_vc;                        // b_edge . w2
// pre-split bf16 weight planes, [n][k] layout (B operand, col-major)
__device__ __nv_bfloat16 g_wth_node[128 * 128], g_wtl_node[128 * 128];
__device__ __nv_bfloat16 g_wth_edge[128 * 64],  g_wtl_edge[128 * 64];
__device__ __nv_bfloat16 g_wth_gnn[3 * 128 * 256], g_wtl_gnn[3 * 128 * 256];

__device__ __forceinline__ void split_store(float x, __nv_bfloat16* ph, __nv_bfloat16* pl) {
    __nv_bfloat16 h = __float2bfloat16(x);
    *ph = h;
    *pl = __float2bfloat16(x - __bfloat162float(h));
}

// ---------------- fused prologue: zeros + transposes + ve ----------------
// flat index space:
//  [0, 1600000)             zero g_agg (float4; NN*128/4)
//  [1600000, 2400000)       zero g_ef_sum (float4; NN*64/4)
//  [2400000, 2412500)       zero g_indeg (float4)
//  [2412500, 2428884)       transpose+split W_node (16384)
//  [2428884, 2437076)       transpose+split W_edge (8192)
//  [2437076, 2535380)       transpose+split W_gnn (98304)
//  [2535380, 2535444)       ve (64)
#define PREP_TOTAL 2535444
__global__ void prep_kernel(const float* __restrict__ W_node,
                            const float* __restrict__ W_edge,
                            const float* __restrict__ W_gnn,
                            const float* __restrict__ b_edge,
                            const float* __restrict__ W_top)
{
    int i = blockIdx.x * blockDim.x + threadIdx.x;
    if (i < 1600000) {
        reinterpret_cast<float4*>(g_agg)[i] = make_float4(0.f, 0.f, 0.f, 0.f);
    } else if (i < 2400000) {
        reinterpret_cast<float4*>(g_ef_sum)[i - 1600000] = make_float4(0.f, 0.f, 0.f, 0.f);
    } else if (i < 2412500) {
        reinterpret_cast<float4*>(g_indeg)[i - 2400000] = make_float4(0.f, 0.f, 0.f, 0.f);
    } else if (i < 2428884) {
        int j = i - 2412500;
        int k = j >> 7, n = j & 127;
        split_store(W_node[j], &g_wth_node[n * 128 + k], &g_wtl_node[n * 128 + k]);
    } else if (i < 2437076) {
        int j = i - 2428884;
        int k = j >> 7, n = j & 127;
        split_store(W_edge[j], &g_wth_edge[n * 64 + k], &g_wtl_edge[n * 64 + k]);
    } else if (i < 2535380) {
        int j = i - 2437076;
        int l = j / 32768, r = j % 32768;
        int k = r >> 7, n = r & 127;
        split_store(W_gnn[j], &g_wth_gnn[l * 32768 + n * 256 + k],
                              &g_wtl_gnn[l * 32768 + n * 256 + k]);
    } else if (i < 2535444) {
        int k = i - 2535380;
        float s = 0.f;
        for (int n = 0; n < 128; n++) s += W_edge[k * 128 + n] * W_top[256 + n];
        g_ve[k] = s;
        if (k == 0) {
            float c = 0.f;
            for (int n = 0; n < 128; n++) c += b_edge[n] * W_top[256 + n];
            g_vc = c;
        }
    }
}

// ---------------- edge feature sum + edot (16 lanes per edge) ----------------
__global__ void __launch_bounds__(256)
edge_sum_kernel(const float* __restrict__ ef, const int* __restrict__ dst_idx)
{
    int t = blockIdx.x * blockDim.x + threadIdx.x;
    int e = t >> 4;
    int l = t & 15;
    if (e >= NE) return;

    float4 v  = *reinterpret_cast<const float4*>(ef + (size_t)e * 64 + l * 4);
    float4 ve = *reinterpret_cast<const float4*>(g_ve + l * 4);
    float p = v.x * ve.x + v.y * ve.y + v.z * ve.z + v.w * ve.w;
#pragma unroll
    for (int o = 1; o < 16; o <<= 1) p += __shfl_xor_sync(0xffffffffu, p, o);

    int d = dst_idx[e];
    if (l == 0) {
        g_edot[e] = p + g_vc;
        atomicAdd(&g_indeg[d], 1.f);
    }
    atomicAdd(reinterpret_cast<float4*>(g_ef_sum + (size_t)d * 64 + l * 4), v);
}

// ---------------- mma / ldmatrix / cp.async / bf16 helpers ----------------
#define MMA_BF16(d, a0, a1, a2, a3, b0, b1)                                    \
    asm volatile(                                                              \
        "mma.sync.aligned.m16n8k16.row.col.f32.bf16.bf16.f32 "                 \
        "{%0,%1,%2,%3}, {%4,%5,%6,%7}, {%8,%9}, {%0,%1,%2,%3};"                \
        : "+f"((d)[0]), "+f"((d)[1]), "+f"((d)[2]), "+f"((d)[3])               \
        : "r"(a0), "r"(a1), "r"(a2), "r"(a3), "r"(b0), "r"(b1))

#define LDSM_X4(R, addr)                                                       \
    asm volatile("ldmatrix.sync.aligned.m8n8.x4.shared.b16 {%0,%1,%2,%3}, [%4];" \
        : "=r"((R)[0]), "=r"((R)[1]), "=r"((R)[2]), "=r"((R)[3]) : "r"(addr))

#define ST_V2(addr, x, y)                                                      \
    asm volatile("st.shared.v2.u32 [%0], {%1,%2};" :: "r"(addr), "r"(x), "r"(y))

#define CP_ASYNC16(saddr, gptr) \
    asm volatile("cp.async.cg.shared.global [%0], [%1], 16;" :: "r"(saddr), "l"(gptr))
#define CP_COMMIT() asm volatile("cp.async.commit_group;")
#define CP_WAIT0()  asm volatile("cp.async.wait_group 0;")

__device__ __forceinline__ uint32_t bf16x2_split(float2 f, float2& rem) {
    uint32_t h;
    asm("cvt.rn.bf16x2.f32 %0, %1, %2;" : "=r"(h) : "f"(f.y), "f"(f.x));
    float hx = __uint_as_float(h << 16);
    float hy = __uint_as_float(h & 0xFFFF0000u);
    rem.x = f.x - hx;
    rem.y = f.y - hy;
    return h;
}
__device__ __forceinline__ uint32_t bf16x2_pack(float2 f) {
    uint32_t h;
    asm("cvt.rn.bf16x2.f32 %0, %1, %2;" : "=r"(h) : "f"(f.y), "f"(f.x));
    return h;
}

// =====================================================================
// Fused bf16x2-split GEMM.
// MODE 0 (node embed):  write g_node_h; a = y.w0, b = y.w1
// MODE 2 (update):      A = [node_h | g_agg + g_agg_e]; x = node_h + (acc+bias);
//                       LayerNorm+ReLU -> dest; if doab: a,b dots AND re-zero
//                       this CTA's g_agg rows for the next layer
// MODE 3 (agg_e):       A = ef_sum [NN,64]; out = acc + indeg[r]*bias -> dest
// =====================================================================
template <int KTOT, int MODE>
__global__ void __launch_bounds__(256, 2)
mma_gemm_kernel(const float* __restrict__ A,
                const __nv_bfloat16* __restrict__ WTH,
                const __nv_bfloat16* __restrict__ WTL,
                const float* __restrict__ bias,
                int M,
                const float* __restrict__ aux,    // MODE0/2: W_top; MODE3: indeg
                const float* __restrict__ lns,
                const float* __restrict__ lnb,
                float* __restrict__ dest,
                int doab)
{
    extern __shared__ float smem[];
    constexpr int NCH = KTOT / 32;
    constexpr int PITCH = 80;
    constexpr int PLANE = 128 * PITCH;
    constexpr int OFF_AH = 0, OFF_AL = PLANE, OFF_BH = 2 * PLANE, OFF_BL = 3 * PLANE;
    constexpr int BUF = 4 * PLANE;

    const int tid   = threadIdx.x;
    const int wid   = tid >> 5;
    const int lane  = tid & 31;
    const int warpM = wid >> 1;
    const int warpN = wid & 1;
    const int lq    = lane >> 2;
    const int lr    = lane & 3;
    const int row0  = blockIdx.x * 128;

    const uint32_t sbase = (uint32_t)__cvta_generic_to_shared(smem);

    float acc[2][8][4];
#pragma unroll
    for (int i = 0; i < 2; i++)
#pragma unroll
        for (int j = 0; j < 8; j++)
#pragma unroll
            for (int q = 0; q < 4; q++) acc[i][j][q] = 0.f;

    float4 va[4];
    auto loadA = [&](int kc) {
#pragma unroll
        for (int l = 0; l < 4; l++) {
            int idx = tid + l * 256;
            int r = idx >> 3;
            int kq = (idx & 7) * 4;
            int grow = row0 + r;
            if (grow >= M) grow = M - 1;
            if (MODE == 2) {
                if (kc < 4) {
                    va[l] = *reinterpret_cast<const float4*>(
                        g_node_h + (size_t)grow * 128 + kc * 32 + kq);
                } else {
                    float4 x = *reinterpret_cast<const float4*>(
                        g_agg + (size_t)grow * 128 + (kc - 4) * 32 + kq);
                    float4 y = *reinterpret_cast<const float4*>(
                        g_agg_e + (size_t)grow * 128 + (kc - 4) * 32 + kq);
                    va[l] = make_float4(x.x + y.x, x.y + y.y, x.z + y.z, x.w + y.w);
                }
            } else {
                va[l] = *reinterpret_cast<const float4*>(
                    A + (size_t)grow * KTOT + kc * 32 + kq);
            }
        }
    };
    auto storeA = [&](int buf) {
        const uint32_t bufo = sbase + buf * BUF;
#pragma unroll
        for (int l = 0; l < 4; l++) {
            int idx = tid + l * 256;
            int r = idx >> 3;
            int kq = (idx & 7) * 4;
            uint32_t off = (uint32_t)(r * PITCH + kq * 2);
            float2 rm0, rm1;
            uint32_t h0 = bf16x2_split(make_float2(va[l].x, va[l].y), rm0);
            uint32_t h1 = bf16x2_split(make_float2(va[l].z, va[l].w), rm1);
            ST_V2(bufo + OFF_AH + off, h0, h1);
            ST_V2(bufo + OFF_AL + off, bf16x2_pack(rm0), bf16x2_pack(rm1));
        }
    };
    auto fillB = [&](int kc, int buf) {
        const uint32_t bufo = sbase + buf * BUF;
#pragma unroll
        for (int l = 0; l < 2; l++) {
            int gr = tid + l * 256;
            int row = gr >> 2;
            int seg = gr & 3;
            uint32_t soff = (uint32_t)(row * PITCH + seg * 16);
            const __nv_bfloat16* sh = WTH + (size_t)row * KTOT + kc * 32 + seg * 8;
            const __nv_bfloat16* sl = WTL + (size_t)row * KTOT + kc * 32 + seg * 8;
            CP_ASYNC16(bufo + OFF_BH + soff, sh);
            CP_ASYNC16(bufo + OFF_BL + soff, sl);
        }
        CP_COMMIT();
    };

    loadA(0);
    fillB(0, 0);
    storeA(0);
    CP_WAIT0();
    __syncthreads();

    const int g   = lane & 15;
    const int hh  = lane >> 4;
    const int q8  = lane & 7;
    const int seg = (lane >> 3) & 3;

    for (int kc = 0; kc < NCH; kc++) {
        const int cur = kc & 1;
        if (kc + 1 < NCH) {
            loadA(kc + 1);
            fillB(kc + 1, cur ^ 1);
        }

        const uint32_t bufo = sbase + cur * BUF;
#pragma unroll
        for (int ks = 0; ks < 2; ks++) {
            uint32_t ah[2][4], al[2][4];
#pragma unroll
            for (int tm = 0; tm < 2; tm++) {
                uint32_t ra = bufo + OFF_AH
                    + (uint32_t)((warpM * 32 + tm * 16 + g) * PITCH + ks * 32 + hh * 16);
                LDSM_X4(ah[tm], ra);
                LDSM_X4(al[tm], ra + (OFF_AL - OFF_AH));
            }
#pragma unroll
            for (int p = 0; p < 4; p++) {
                int n = warpN * 64 + (2 * p + (seg >> 1)) * 8 + q8;
                uint32_t rb = bufo + OFF_BH
                    + (uint32_t)(n * PITCH + ks * 32 + (seg & 1) * 16);
                uint32_t bh[4], bl[4];
                LDSM_X4(bh, rb);
                LDSM_X4(bl, rb + (OFF_BL - OFF_BH));
                MMA_BF16(acc[0][2 * p],     ah[0][0], ah[0][1], ah[0][2], ah[0][3], bh[0], bh[1]);
                MMA_BF16(acc[1][2 * p],     ah[1][0], ah[1][1], ah[1][2], ah[1][3], bh[0], bh[1]);
                MMA_BF16(acc[0][2 * p + 1], ah[0][0], ah[0][1], ah[0][2], ah[0][3], bh[2], bh[3]);
                MMA_BF16(acc[1][2 * p + 1], ah[1][0], ah[1][1], ah[1][2], ah[1][3], bh[2], bh[3]);
                MMA_BF16(acc[0][2 * p],     al[0][0], al[0][1], al[0][2], al[0][3], bh[0], bh[1]);
                MMA_BF16(acc[1][2 * p],     al[1][0], al[1][1], al[1][2], al[1][3], bh[0], bh[1]);
                MMA_BF16(acc[0][2 * p + 1], al[0][0], al[0][1], al[0][2], al[0][3], bh[2], bh[3]);
                MMA_BF16(acc[1][2 * p + 1], al[1][0], al[1][1], al[1][2], al[1][3], bh[2], bh[3]);
                MMA_BF16(acc[0][2 * p],     ah[0][0], ah[0][1], ah[0][2], ah[0][3], bl[0], bl[1]);
                MMA_BF16(acc[1][2 * p],     ah[1][0], ah[1][1], ah[1][2], ah[1][3], bl[0], bl[1]);
                MMA_BF16(acc[0][2 * p + 1], ah[0][0], ah[0][1], ah[0][2], ah[0][3], bl[2], bl[3]);
                MMA_BF16(acc[1][2 * p + 1], ah[1][0], ah[1][1], ah[1][2], ah[1][3], bl[2], bl[3]);
            }
        }
        if (kc + 1 < NCH) storeA(cur ^ 1);
        CP_WAIT0();
        __syncthreads();
    }

    // ---------------- epilogue ----------------
    if (MODE != 3) {
#pragma unroll
        for (int tn = 0; tn < 8; tn++) {
            int col = warpN * 64 + tn * 8 + lr * 2;
            float bx = bias[col], by = bias[col + 1];
#pragma unroll
            for (int tm = 0; tm < 2; tm++) {
                acc[tm][tn][0] += bx; acc[tm][tn][1] += by;
                acc[tm][tn][2] += bx; acc[tm][tn][3] += by;
            }
        }
    }
    int rl[2][2], rg[2][2];
#pragma unroll
    for (int tm = 0; tm < 2; tm++) {
        rl[tm][0] = warpM * 32 + tm * 16 + lq;
        rl[tm][1] = rl[tm][0] + 8;
        rg[tm][0] = row0 + rl[tm][0];
        rg[tm][1] = row0 + rl[tm][1];
    }

    float* red0 = smem;
    float* red1 = smem + 128;

    if (MODE == 0) {
        float pa[2][2] = {{0,0},{0,0}}, pb[2][2] = {{0,0},{0,0}};
#pragma unroll
        for (int tn = 0; tn < 8; tn++) {
            int col = warpN * 64 + tn * 8 + lr * 2;
            float w0x = aux[col], w0y = aux[col + 1];
            float w1x = aux[128 + col], w1y = aux[128 + col + 1];
#pragma unroll
            for (int tm = 0; tm < 2; tm++) {
#pragma unroll
                for (int h = 0; h < 2; h++) {
                    float vx = acc[tm][tn][h * 2], vy = acc[tm][tn][h * 2 + 1];
                    if (rg[tm][h] < M)
                        *reinterpret_cast<float2*>(g_node_h + (size_t)rg[tm][h] * 128 + col)
                            = make_float2(vx, vy);
                    pa[tm][h] += vx * w0x + vy * w0y;
                    pb[tm][h] += vx * w1x + vy * w1y;
                }
            }
        }
        if (tid < 128) { red0[tid] = 0.f; red1[tid] = 0.f; }
        __syncthreads();
#pragma unroll
        for (int tm = 0; tm < 2; tm++)
#pragma unroll
            for (int h = 0; h < 2; h++) {
#pragma unroll
                for (int o = 1; o <= 2; o <<= 1) {
                    pa[tm][h] += __shfl_xor_sync(0xffffffffu, pa[tm][h], o);
                    pb[tm][h] += __shfl_xor_sync(0xffffffffu, pb[tm][h], o);
                }
                if (lr == 0) {
                    atomicAdd(&red0[rl[tm][h]], pa[tm][h]);
                    atomicAdd(&red1[rl[tm][h]], pb[tm][h]);
                }
            }
        __syncthreads();
        if (tid < 128 && row0 + tid < M) {
            g_a[row0 + tid] = red0[tid];
            g_b[row0 + tid] = red1[tid];
        }
    }
    else if (MODE == 3) {
        float ind[2][2];
#pragma unroll
        for (int tm = 0; tm < 2; tm++)
#pragma unroll
            for (int h = 0; h < 2; h++)
                ind[tm][h] = (rg[tm][h] < M) ? aux[rg[tm][h]] : 0.f;
#pragma unroll
        for (int tn = 0; tn < 8; tn++) {
            int col = warpN * 64 + tn * 8 + lr * 2;
            float bx = bias[col], by = bias[col + 1];
#pragma unroll
            for (int tm = 0; tm < 2; tm++) {
#pragma unroll
                for (int h = 0; h < 2; h++) {
                    if (rg[tm][h] < M) {
                        float2 v = make_float2(acc[tm][tn][h * 2] + ind[tm][h] * bx,
                                               acc[tm][tn][h * 2 + 1] + ind[tm][h] * by);
                        *reinterpret_cast<float2*>(dest + (size_t)rg[tm][h] * 128 + col) = v;
                    }
                }
            }
        }
    }
    else {
        float ps[2][2] = {{0,0},{0,0}}, pq[2][2] = {{0,0},{0,0}};
#pragma unroll
        for (int tn = 0; tn < 8; tn++) {
            int col = warpN * 64 + tn * 8 + lr * 2;
#pragma unroll
            for (int tm = 0; tm < 2; tm++) {
#pragma unroll
                for (int h = 0; h < 2; h++) {
                    float2 res = (rg[tm][h] < M)
                        ? *reinterpret_cast<const float2*>(g_node_h + (size_t)rg[tm][h] * 128 + col)
                        : make_float2(0.f, 0.f);
                    float x0 = acc[tm][tn][h * 2] + res.x;
                    float x1 = acc[tm][tn][h * 2 + 1] + res.y;
                    acc[tm][tn][h * 2] = x0;
                    acc[tm][tn][h * 2 + 1] = x1;
                    ps[tm][h] += x0 + x1;
                    pq[tm][h] += x0 * x0 + x1 * x1;
                }
            }
        }
        if (tid < 128) { red0[tid] = 0.f; red1[tid] = 0.f; }
        __syncthreads();
#pragma unroll
        for (int tm = 0; tm < 2; tm++)
#pragma unroll
            for (int h = 0; h < 2; h++) {
#pragma unroll
                for (int o = 1; o <= 2; o <<= 1) {
                    ps[tm][h] += __shfl_xor_sync(0xffffffffu, ps[tm][h], o);
                    pq[tm][h] += __shfl_xor_sync(0xffffffffu, pq[tm][h], o);
                }
                if (lr == 0) {
                    atomicAdd(&red0[rl[tm][h]], ps[tm][h]);
                    atomicAdd(&red1[rl[tm][h]], pq[tm][h]);
                }
            }
        __syncthreads();
        float mean_[2][2], inv_[2][2];
#pragma unroll
        for (int tm = 0; tm < 2; tm++)
#pragma unroll
            for (int h = 0; h < 2; h++) {
                float m = red0[rl[tm][h]] * (1.f / 128.f);
                float var = red1[rl[tm][h]] * (1.f / 128.f) - m * m;
                mean_[tm][h] = m;
                inv_[tm][h] = rsqrtf(fmaxf(var, 0.f) + 1e-6f);
            }
        float pa[2][2] = {{0,0},{0,0}}, pb[2][2] = {{0,0},{0,0}};
#pragma unroll
        for (int tn = 0; tn < 8; tn++) {
            int col = warpN * 64 + tn * 8 + lr * 2;
            float scx = lns[col], scy = lns[col + 1];
            float bix = lnb[col], biy = lnb[col + 1];
            float w0x = aux[col], w0y = aux[col + 1];
            float w1x = aux[128 + col], w1y = aux[128 + col + 1];
#pragma unroll
            for (int tm = 0; tm < 2; tm++) {
#pragma unroll
                for (int h = 0; h < 2; h++) {
                    float y0 = fmaxf(0.f, (acc[tm][tn][h * 2] - mean_[tm][h]) * inv_[tm][h] * scx + bix);
                    float y1 = fmaxf(0.f, (acc[tm][tn][h * 2 + 1] - mean_[tm][h]) * inv_[tm][h] * scy + biy);
                    if (rg[tm][h] < M)
                        *reinterpret_cast<float2*>(dest + (size_t)rg[tm][h] * 128 + col)
                            = make_float2(y0, y1);
                    pa[tm][h] += y0 * w0x + y1 * w0y;
                    pb[tm][h] += y0 * w1x + y1 * w1y;
                }
            }
        }
        if (doab) {
            __syncthreads();
            if (tid < 128) { red0[tid] = 0.f; red1[tid] = 0.f; }
            __syncthreads();
#pragma unroll
            for (int tm = 0; tm < 2; tm++)
#pragma unroll
                for (int h = 0; h < 2; h++) {
#pragma unroll
                    for (int o = 1; o <= 2; o <<= 1) {
                        pa[tm][h] += __shfl_xor_sync(0xffffffffu, pa[tm][h], o);
                        pb[tm][h] += __shfl_xor_sync(0xffffffffu, pb[tm][h], o);
                    }
                    if (lr == 0) {
                        atomicAdd(&red0[rl[tm][h]], pa[tm][h]);
                        atomicAdd(&red1[rl[tm][h]], pb[tm][h]);
                    }
                }
            __syncthreads();
            if (tid < 128 && row0 + tid < M) {
                g_a[row0 + tid] = red0[tid];
                g_b[row0 + tid] = red1[tid];
            }
            // re-zero this CTA's g_agg rows for the next layer's scatter
            float4 z = make_float4(0.f, 0.f, 0.f, 0.f);
#pragma unroll
            for (int c = 0; c < 4; c++) {
#pragma unroll
                for (int l = 0; l < 4; l++) {
                    int idx = tid + l * 256;
                    int r = idx >> 3;
                    int kq = (idx & 7) * 4;
                    int grow = row0 + r;
                    if (grow < M)
                        *reinterpret_cast<float4*>(
                            g_agg + (size_t)grow * 128 + c * 32 + kq) = z;
                }
            }
        }
    }
}

// ---------------- per-layer edge phase: gate + scatter src_f*wgt ----------------
__global__ void __launch_bounds__(256)
edge_kernel(const int* __restrict__ src_idx, const int* __restrict__ dst_idx,
            const float* __restrict__ b_top, float* __restrict__ w_out)
{
    int e = (blockIdx.x * blockDim.x + threadIdx.x) >> 5;
    int lane = threadIdx.x & 31;
    if (e >= NE) return;

    int s = src_idx[e];
    int d = dst_idx[e];

    float wgt;
    if (lane == 0) {
        float g = g_a[s] + g_b[d] + g_edot[e] + b_top[0];
        wgt = 1.f / (1.f + __expf(-g));
    }
    wgt = __shfl_sync(0xffffffffu, wgt, 0);

    float4 sv = *reinterpret_cast<const float4*>(g_node_h + (size_t)s * 128 + lane * 4);
    float4 msg = make_float4(sv.x * wgt, sv.y * wgt, sv.z * wgt, sv.w * wgt);
    atomicAdd(reinterpret_cast<float4*>(g_agg + (size_t)d * 128 + lane * 4), msg);

    if (w_out != nullptr && lane == 0) w_out[e] = wgt;
}

// ---------------- launch ----------------
extern "C" void kernel_launch(void* const* d_in, const int* in_sizes, int n_in,
                              void* d_out, int out_size)
{
    const float* nf     = (const float*)d_in[0];
    const float* ef     = (const float*)d_in[1];
    const int*   ei     = (const int*)  d_in[2];
    const float* W_node = (const float*)d_in[3];
    const float* b_node = (const float*)d_in[4];
    const float* W_edge = (const float*)d_in[5];
    const float* b_edge = (const float*)d_in[6];
    const float* W_gnn  = (const float*)d_in[7];
    const float* b_gnn  = (const float*)d_in[8];
    const float* W_top  = (const float*)d_in[9];
    const float* b_top  = (const float*)d_in[10];
    const float* ln_s   = (const float*)d_in[11];
    const float* ln_b   = (const float*)d_in[12];

    float* out       = (float*)d_out;
    float* out_nodes = out;
    float* out_w     = out + (size_t)NN * 128;

    const int* src = ei;
    const int* dst = ei + NE;

    const int SMEM_SZ = 2 * 4 * 128 * 80;   // 81920 B
    cudaFuncSetAttribute(mma_gemm_kernel<128, 0>, cudaFuncAttributeMaxDynamicSharedMemorySize, SMEM_SZ);
    cudaFuncSetAttribute(mma_gemm_kernel<64, 3>,  cudaFuncAttributeMaxDynamicSharedMemorySize, SMEM_SZ);
    cudaFuncSetAttribute(mma_gemm_kernel<256, 2>, cudaFuncAttributeMaxDynamicSharedMemorySize, SMEM_SZ);

    __nv_bfloat16 *wthn = nullptr, *wtln = nullptr, *wthe = nullptr, *wtle = nullptr;
    __nv_bfloat16 *wthg = nullptr, *wtlg = nullptr;
    cudaGetSymbolAddress((void**)&wthn, g_wth_node);
    cudaGetSymbolAddress((void**)&wtln, g_wtl_node);
    cudaGetSymbolAddress((void**)&wthe, g_wth_edge);
    cudaGetSymbolAddress((void**)&wtle, g_wtl_edge);
    cudaGetSymbolAddress((void**)&wthg, g_wth_gnn);
    cudaGetSymbolAddress((void**)&wtlg, g_wtl_gnn);
    float* nodeh = nullptr; float* aggep = nullptr;
    float* efsum = nullptr; float* indeg = nullptr;
    cudaGetSymbolAddress((void**)&nodeh, g_node_h);
    cudaGetSymbolAddress((void**)&aggep, g_agg_e);
    cudaGetSymbolAddress((void**)&efsum, g_ef_sum);
    cudaGetSymbolAddress((void**)&indeg, g_indeg);

    // second stream + events for fork-join (created once; graph-capture legal)
    static cudaStream_t s2 = nullptr;
    static cudaEvent_t ev_fork = nullptr, ev_es = nullptr, ev_m0 = nullptr, ev_m3 = nullptr;
    if (s2 == nullptr) {
        cudaStreamCreateWithFlags(&s2, cudaStreamNonBlocking);
        cudaEventCreateWithFlags(&ev_fork, cudaEventDisableTiming);
        cudaEventCreateWithFlags(&ev_es, cudaEventDisableTiming);
        cudaEventCreateWithFlags(&ev_m0, cudaEventDisableTiming);
        cudaEventCreateWithFlags(&ev_m3, cudaEventDisableTiming);
    }

    // fused prologue (zeros incl. g_agg + transposes + ve)
    prep_kernel<<<(PREP_TOTAL + 255) / 256, 256>>>(W_node, W_edge, W_gnn, b_edge, W_top);

    // fork: s2 runs MODE0 (node embed) then MODE3 (agg_e) — both off the
    // critical path until their consumers
    cudaEventRecord(ev_fork, 0);
    cudaStreamWaitEvent(s2, ev_fork, 0);
    mma_gemm_kernel<128, 0><<<(NN + 127) / 128, 256, SMEM_SZ, s2>>>(
        nf, wthn, wtln, b_node, NN, W_top, nullptr, nullptr, nullptr, 0);
    cudaEventRecord(ev_m0, s2);

    // main: edge feature sum + edot
    edge_sum_kernel<<<(NE * 16 + 255) / 256, 256>>>(ef, dst);
    cudaEventRecord(ev_es, 0);

    // s2: agg_e GEMM (needs edge_sum); overlaps with edge(0) on main
    cudaStreamWaitEvent(s2, ev_es, 0);
    mma_gemm_kernel<64, 3><<<(NN + 127) / 128, 256, SMEM_SZ, s2>>>(
        efsum, wthe, wtle, b_edge, NN, indeg, nullptr, nullptr, aggep, 0);
    cudaEventRecord(ev_m3, s2);

    // main: edge(0) needs a,b (MODE0) + edot + node_h — not agg_e
    cudaStreamWaitEvent(0, ev_m0, 0);

    for (int i = 0; i < 3; i++) {
        edge_kernel<<<(NE * 32 + 255) / 256, 256>>>(
            src, dst, b_top, (i == 2) ? out_w : nullptr);
        if (i == 0) cudaStreamWaitEvent(0, ev_m3, 0);   // MODE2 needs agg_e
        mma_gemm_kernel<256, 2><<<(NN + 127) / 128, 256, SMEM_SZ>>>(
            nullptr, wthg + (size_t)i * 128 * 256, wtlg + (size_t)i * 128 * 256,
            b_gnn + i * 128, NN,
            W_top, ln_s + i * 128, ln_b + i * 128,
            (i == 2) ? out_nodes : nodeh, (i < 2) ? 1 : 0);
    }
}